// round 2
// baseline (speedup 1.0000x reference)
#include <cuda_runtime.h>

// Problem constants
#define B_   8
#define S_   1024
#define D_   2048
#define H_   16
#define DH_  128
#define FF_  8192
#define NTOK (B_*S_)   // 8192

// ---------------- scratch (static device globals; no allocation) ----------
__device__ float g_q[(size_t)NTOK * D_];          // 64 MB
__device__ float g_k[(size_t)NTOK * D_];          // 64 MB
__device__ float g_v[(size_t)NTOK * D_];          // 64 MB
__device__ float g_s[(size_t)B_ * H_ * S_ * S_];  // 512 MB scores
__device__ float g_h[(size_t)NTOK * FF_];         // 256 MB FFN hidden

// ---------------- GEMM ----------------------------------------------------
// C[M,N] = A[M,K] @ op(B) + epilogue
//   TRANSB=true : B is [N,K] row-major (use B^T)  -> "NT" (K-contig both)
//   TRANSB=false: B is [K,N] row-major            -> "NN"
// Batched via blockIdx.z: ptr += (z/HH)*s?b + (z%HH)*s?h
// All M,N multiples of 128, K multiple of 8 (guaranteed by problem shapes).
enum { EPI_NONE = 0, EPI_BIAS = 1, EPI_BIAS_RELU = 2, EPI_SCORE = 3 };

#define BM 128
#define BN 128
#define BKG 8
#define TM 8
#define TN 8

template <bool TRANSB, int EPI>
__global__ void __launch_bounds__(256) gemm_kernel(
    const float* __restrict__ A, int lda, long sAb, long sAh,
    const float* __restrict__ Bm, int ldb, long sBb, long sBh,
    float* __restrict__ C, int ldc, long sCb, long sCh,
    int K, int HH,
    const float* __restrict__ bias,
    const int* __restrict__ mask, float scale)
{
    __shared__ float As[BKG][BM];
    __shared__ float Bs[BKG][BN];

    const int z = blockIdx.z;
    A  += (long)(z / HH) * sAb + (long)(z % HH) * sAh;
    Bm += (long)(z / HH) * sBb + (long)(z % HH) * sBh;
    C  += (long)(z / HH) * sCb + (long)(z % HH) * sCh;

    const int tid = threadIdx.x;
    const int rowBase = blockIdx.y * BM;
    const int colBase = blockIdx.x * BN;

    // global->shared load mapping (one float4 per thread per tile)
    const int la_r = tid >> 1;        // 0..127
    const int la_k = (tid & 1) * 4;   // 0 or 4

    const float* Aptr = A + (long)(rowBase + la_r) * lda + la_k;
    const float* Bptr;
    if (TRANSB) Bptr = Bm + (long)(colBase + la_r) * ldb + la_k;
    else        Bptr = Bm + (long)(tid >> 5) * ldb + colBase + (tid & 31) * 4;

    const int ty = tid >> 4;   // 0..15 (M dir)
    const int tx = tid & 15;   // 0..15 (N dir)

    float acc[TM][TN];
#pragma unroll
    for (int i = 0; i < TM; i++)
#pragma unroll
        for (int j = 0; j < TN; j++) acc[i][j] = 0.f;

    for (int k0 = 0; k0 < K; k0 += BKG) {
        float4 av = *(const float4*)Aptr;
        As[la_k + 0][la_r] = av.x;
        As[la_k + 1][la_r] = av.y;
        As[la_k + 2][la_r] = av.z;
        As[la_k + 3][la_r] = av.w;
        if (TRANSB) {
            float4 bv = *(const float4*)Bptr;
            Bs[la_k + 0][la_r] = bv.x;
            Bs[la_k + 1][la_r] = bv.y;
            Bs[la_k + 2][la_r] = bv.z;
            Bs[la_k + 3][la_r] = bv.w;
        } else {
            *(float4*)&Bs[tid >> 5][(tid & 31) * 4] = *(const float4*)Bptr;
        }
        __syncthreads();

#pragma unroll
        for (int kk = 0; kk < BKG; ++kk) {
            float a[TM], b[TN];
            *(float4*)&a[0] = *(const float4*)&As[kk][ty * TM];
            *(float4*)&a[4] = *(const float4*)&As[kk][ty * TM + 4];
            *(float4*)&b[0] = *(const float4*)&Bs[kk][tx * TN];
            *(float4*)&b[4] = *(const float4*)&Bs[kk][tx * TN + 4];
#pragma unroll
            for (int i = 0; i < TM; i++)
#pragma unroll
                for (int j = 0; j < TN; j++)
                    acc[i][j] += a[i] * b[j];
        }
        __syncthreads();

        Aptr += BKG;
        if (TRANSB) Bptr += BKG;
        else        Bptr += (long)BKG * ldb;
    }

    // epilogue (vectorized stores; N offsets are multiples of 8)
#pragma unroll
    for (int i = 0; i < TM; i++) {
        const int r = rowBase + ty * TM + i;
        float v[TN];
#pragma unroll
        for (int j = 0; j < TN; j++) {
            const int c = colBase + tx * TN + j;
            float t = acc[i][j];
            if (EPI == EPI_BIAS)       t += bias[c];
            else if (EPI == EPI_BIAS_RELU) t = fmaxf(t + bias[c], 0.f);
            else if (EPI == EPI_SCORE) {
                t *= scale;
                if (mask[(long)r * S_ + c] == 0) t = -1e9f;
            }
            v[j] = t;
        }
        float* cp = C + (long)r * ldc + colBase + tx * TN;
        *(float4*)cp       = *(float4*)&v[0];
        *(float4*)(cp + 4) = *(float4*)&v[4];
    }
}

// ---------------- softmax: one warp per 1024-wide row ----------------------
__global__ void __launch_bounds__(256) softmax_kernel(float* __restrict__ s)
{
    const int gw   = (blockIdx.x * blockDim.x + threadIdx.x) >> 5;  // row id
    const int lane = threadIdx.x & 31;
    float* row = s + (size_t)gw * S_;

    float4 v[8];
    float mx = -3.4e38f;
#pragma unroll
    for (int i = 0; i < 8; i++) {
        v[i] = *(const float4*)&row[lane * 4 + i * 128];
        mx = fmaxf(mx, fmaxf(fmaxf(v[i].x, v[i].y), fmaxf(v[i].z, v[i].w)));
    }
#pragma unroll
    for (int o = 16; o; o >>= 1) mx = fmaxf(mx, __shfl_xor_sync(0xffffffffu, mx, o));

    float sum = 0.f;
#pragma unroll
    for (int i = 0; i < 8; i++) {
        v[i].x = __expf(v[i].x - mx);
        v[i].y = __expf(v[i].y - mx);
        v[i].z = __expf(v[i].z - mx);
        v[i].w = __expf(v[i].w - mx);
        sum += v[i].x + v[i].y + v[i].z + v[i].w;
    }
#pragma unroll
    for (int o = 16; o; o >>= 1) sum += __shfl_xor_sync(0xffffffffu, sum, o);

    const float inv = 1.f / sum;
#pragma unroll
    for (int i = 0; i < 8; i++) {
        v[i].x *= inv; v[i].y *= inv; v[i].z *= inv; v[i].w *= inv;
        *(float4*)&row[lane * 4 + i * 128] = v[i];
    }
}

// ---------------- fused residual + LayerNorm -------------------------------
__device__ __forceinline__ float blk_sum(float v, float* sh)
{
#pragma unroll
    for (int o = 16; o; o >>= 1) v += __shfl_xor_sync(0xffffffffu, v, o);
    const int lane = threadIdx.x & 31, w = threadIdx.x >> 5;
    if (lane == 0) sh[w] = v;
    __syncthreads();
    if (w == 0) {
        float t = (lane < 8) ? sh[lane] : 0.f;
#pragma unroll
        for (int o = 4; o; o >>= 1) t += __shfl_xor_sync(0xffu, t, o);
        if (lane == 0) sh[0] = t;
    }
    __syncthreads();
    const float r = sh[0];
    __syncthreads();
    return r;
}

__global__ void __launch_bounds__(256) ln_kernel(
    const float* __restrict__ a, const float* __restrict__ b,
    const float* __restrict__ g, const float* __restrict__ be,
    float* __restrict__ out)
{
    __shared__ float sh[8];
    const int row = blockIdx.x, tid = threadIdx.x;
    const float* pa = a + (size_t)row * D_;
    const float* pb = b + (size_t)row * D_;
    const int c0 = tid * 8;

    float x[8];
    {
        float4 a0 = *(const float4*)&pa[c0], a1 = *(const float4*)&pa[c0 + 4];
        float4 b0 = *(const float4*)&pb[c0], b1 = *(const float4*)&pb[c0 + 4];
        x[0] = a0.x + b0.x; x[1] = a0.y + b0.y; x[2] = a0.z + b0.z; x[3] = a0.w + b0.w;
        x[4] = a1.x + b1.x; x[5] = a1.y + b1.y; x[6] = a1.z + b1.z; x[7] = a1.w + b1.w;
    }
    float s = 0.f;
#pragma unroll
    for (int i = 0; i < 8; i++) s += x[i];
    const float mean = blk_sum(s, sh) * (1.f / D_);

    float vs = 0.f;
#pragma unroll
    for (int i = 0; i < 8; i++) { const float d = x[i] - mean; vs += d * d; }
    const float var = blk_sum(vs, sh) * (1.f / D_);
    const float inv = rsqrtf(var + 1e-5f);

    float4 g0 = *(const float4*)&g[c0],  g1v = *(const float4*)&g[c0 + 4];
    float4 e0 = *(const float4*)&be[c0], e1v = *(const float4*)&be[c0 + 4];
    float4 o0, o1;
    o0.x = (x[0] - mean) * inv * g0.x + e0.x;
    o0.y = (x[1] - mean) * inv * g0.y + e0.y;
    o0.z = (x[2] - mean) * inv * g0.z + e0.z;
    o0.w = (x[3] - mean) * inv * g0.w + e0.w;
    o1.x = (x[4] - mean) * inv * g1v.x + e1v.x;
    o1.y = (x[5] - mean) * inv * g1v.y + e1v.y;
    o1.z = (x[6] - mean) * inv * g1v.z + e1v.z;
    o1.w = (x[7] - mean) * inv * g1v.w + e1v.w;
    float* po = out + (size_t)row * D_;
    *(float4*)&po[c0] = o0;
    *(float4*)&po[c0 + 4] = o1;
}

// ---------------- launch ----------------------------------------------------
extern "C" void kernel_launch(void* const* d_in, const int* in_sizes, int n_in,
                              void* d_out, int out_size)
{
    const float* x    = (const float*)d_in[0];
    const int*   mask = (const int*)  d_in[1];
    const float* Wq = (const float*)d_in[2];  const float* bq = (const float*)d_in[3];
    const float* Wk = (const float*)d_in[4];  const float* bk = (const float*)d_in[5];
    const float* Wv = (const float*)d_in[6];  const float* bv = (const float*)d_in[7];
    const float* Wo = (const float*)d_in[8];  const float* bo = (const float*)d_in[9];
    const float* W1 = (const float*)d_in[10]; const float* b1 = (const float*)d_in[11];
    const float* W2 = (const float*)d_in[12]; const float* b2 = (const float*)d_in[13];
    const float* g1 = (const float*)d_in[14]; const float* be1 = (const float*)d_in[15];
    const float* g2 = (const float*)d_in[16]; const float* be2 = (const float*)d_in[17];
    float* out = (float*)d_out;

    float *q, *k, *v, *sc, *hb;
    cudaGetSymbolAddress((void**)&q,  g_q);
    cudaGetSymbolAddress((void**)&k,  g_k);
    cudaGetSymbolAddress((void**)&v,  g_v);
    cudaGetSymbolAddress((void**)&sc, g_s);
    cudaGetSymbolAddress((void**)&hb, g_h);

    const float scale = 0.08838834764831843f;  // 1/sqrt(128)
    const long SD  = (long)S_ * D_;
    const long SS  = (long)S_ * S_;

    // QKV projections: [8192,2048] = x @ W^T + b
    dim3 gproj(D_ / BN, NTOK / BM, 1);
    gemm_kernel<true, EPI_BIAS><<<gproj, 256>>>(x, D_, 0, 0, Wq, D_, 0, 0,
                                                q, D_, 0, 0, D_, 1, bq, nullptr, 0.f);
    gemm_kernel<true, EPI_BIAS><<<gproj, 256>>>(x, D_, 0, 0, Wk, D_, 0, 0,
                                                k, D_, 0, 0, D_, 1, bk, nullptr, 0.f);
    gemm_kernel<true, EPI_BIAS><<<gproj, 256>>>(x, D_, 0, 0, Wv, D_, 0, 0,
                                                v, D_, 0, 0, D_, 1, bv, nullptr, 0.f);

    // scores[b,h] = q_bh @ k_bh^T * scale, masked  -> [1024,1024] x 128
    dim3 gsc(S_ / BN, S_ / BM, B_ * H_);
    gemm_kernel<true, EPI_SCORE><<<gsc, 256>>>(q, D_, SD, DH_, k, D_, SD, DH_,
                                               sc, S_, (long)H_ * SS, SS,
                                               DH_, H_, nullptr, mask, scale);

    // softmax over last axis: 131072 rows, 1 warp each
    softmax_kernel<<<(B_ * H_ * S_) / 8, 256>>>(sc);

    // attn @ V  -> concat heads back into g_q ([8192,2048])
    dim3 gav(DH_ / BN, S_ / BM, B_ * H_);
    gemm_kernel<false, EPI_NONE><<<gav, 256>>>(sc, S_, (long)H_ * SS, SS,
                                               v, D_, SD, DH_,
                                               q, D_, SD, DH_,
                                               S_, H_, nullptr, nullptr, 0.f);

    // output projection -> g_k
    gemm_kernel<true, EPI_BIAS><<<gproj, 256>>>(q, D_, 0, 0, Wo, D_, 0, 0,
                                                k, D_, 0, 0, D_, 1, bo, nullptr, 0.f);

    // x1 = LN(attn_proj + x) -> g_v
    ln_kernel<<<NTOK, 256>>>(k, x, g1, be1, v);

    // h = relu(x1 @ W1^T + b1) -> g_h  [8192,8192]
    dim3 gff1(FF_ / BN, NTOK / BM, 1);
    gemm_kernel<true, EPI_BIAS_RELU><<<gff1, 256>>>(v, D_, 0, 0, W1, D_, 0, 0,
                                                    hb, FF_, 0, 0, D_, 1, b1, nullptr, 0.f);

    // ffn = h @ W2^T + b2 -> g_k  [8192,2048]
    gemm_kernel<true, EPI_BIAS><<<gproj, 256>>>(hb, FF_, 0, 0, W2, FF_, 0, 0,
                                                k, D_, 0, 0, FF_, 1, b2, nullptr, 0.f);

    // out = LN(ffn + x1)
    ln_kernel<<<NTOK, 256>>>(k, v, g2, be2, out);
}

// round 4
// speedup vs baseline: 3.2288x; 3.2288x over previous
#include <cuda_runtime.h>
#include <cstdint>

#define B_   8
#define S_   1024
#define D_   2048
#define H_   16
#define DH_  128
#define FF_  8192
#define NTOK (B_*S_)   // 8192

// ---------------- scratch ----------------
__device__ float g_q[(size_t)NTOK * D_];
__device__ float g_k[(size_t)NTOK * D_];
__device__ float g_v[(size_t)NTOK * D_];
__device__ float g_s[(size_t)B_ * H_ * S_ * S_];
__device__ float g_h[(size_t)NTOK * FF_];

enum { EPI_NONE = 0, EPI_BIAS = 1, EPI_BIAS_RELU = 2, EPI_SCORE = 3 };

__device__ __forceinline__ uint32_t smem_u32(const void* p) {
    uint32_t a;
    asm("{ .reg .u64 t; cvta.to.shared.u64 t, %1; cvt.u32.u64 %0, t; }" : "=r"(a) : "l"(p));
    return a;
}
__device__ __forceinline__ uint32_t f2tf32(float f) {
    uint32_t r;
    asm("cvt.rna.tf32.f32 %0, %1;" : "=r"(r) : "f"(f));
    return r;
}

// ---------------- tf32 mma.sync GEMM ----------------
// C[128x128 tile] = A[M,K] @ op(B) + epilogue
//  TRB=false: B is [N,K] row-major (K-contiguous)  -> direct cp.async
//  TRB=true : B is [K,N] row-major (N-contiguous)  -> register transpose into smem
// Batched via blockIdx.z.
template <bool TRB, int EPI>
__global__ void __launch_bounds__(256) mma_gemm(
    const float* __restrict__ A, int lda, long sAb, long sAh,
    const float* __restrict__ Bm, int ldb, long sBb, long sBh,
    float* __restrict__ C, int ldc, long sCb, long sCh,
    int K, int HH, const float* __restrict__ bias,
    const int* __restrict__ mask, float scale)
{
    extern __shared__ float sm[];
    const int tid = threadIdx.x;

    const int z = blockIdx.z;
    A  += (long)(z / HH) * sAb + (long)(z % HH) * sAh;
    Bm += (long)(z / HH) * sBb + (long)(z % HH) * sBh;
    C  += (long)(z / HH) * sCb + (long)(z % HH) * sCh;

    const int rowBase = blockIdx.y * 128;
    const int colBase = blockIdx.x * 128;

    constexpr int LDS_ = 36;              // padded row stride (floats)
    constexpr int TILE_F = 128 * LDS_;    // floats per buffer
    float* sA = sm;                       // [2][128][36]
    float* sB = sm + 2 * TILE_F;          // [2][128][36]
    const uint32_t sAaddr = smem_u32(sm);
    const uint32_t sBaddr = sAaddr + 2 * TILE_F * 4;

    const int lane = tid & 31, wid = tid >> 5;
    const int wm = (wid & 1) * 64;        // warp row offset within tile
    const int wn = (wid >> 1) * 32;       // warp col offset within tile
    const int g  = lane >> 2;             // group id (0..7)
    const int qt = lane & 3;              // thread-in-group (0..3)

    float acc[4][4][4];
#pragma unroll
    for (int i = 0; i < 4; i++)
#pragma unroll
        for (int j = 0; j < 4; j++)
#pragma unroll
            for (int u = 0; u < 4; u++) acc[i][j][u] = 0.f;

    auto cpA = [&](int k0, int buf) {
#pragma unroll
        for (int j = 0; j < 4; j++) {
            int f = tid + 256 * j; int r = f >> 3, c4 = (f & 7) * 4;
            const float* src = A + (long)(rowBase + r) * lda + k0 + c4;
            uint32_t dst = sAaddr + (uint32_t)(buf * TILE_F + r * LDS_ + c4) * 4;
            asm volatile("cp.async.cg.shared.global [%0], [%1], 16;" :: "r"(dst), "l"(src));
        }
    };
    auto cpB = [&](int k0, int buf) {      // !TRB path
#pragma unroll
        for (int j = 0; j < 4; j++) {
            int f = tid + 256 * j; int r = f >> 3, c4 = (f & 7) * 4;
            const float* src = Bm + (long)(colBase + r) * ldb + k0 + c4;
            uint32_t dst = sBaddr + (uint32_t)(buf * TILE_F + r * LDS_ + c4) * 4;
            asm volatile("cp.async.cg.shared.global [%0], [%1], 16;" :: "r"(dst), "l"(src));
        }
    };
    float4 brg[4];
    auto ldBreg = [&](int k0) {            // TRB: load 32 k-rows x 128 n-cols
#pragma unroll
        for (int j = 0; j < 4; j++) {
            int f = tid + 256 * j; int kl = f >> 5, n4 = (f & 31) * 4;
            brg[j] = *(const float4*)(Bm + (long)(k0 + kl) * ldb + colBase + n4);
        }
    };
    auto stBreg = [&](int buf) {           // TRB: transpose into [n][k] smem
#pragma unroll
        for (int j = 0; j < 4; j++) {
            int f = tid + 256 * j; int kl = f >> 5, n4 = (f & 31) * 4;
            float* d = sB + buf * TILE_F + kl;
            d[(n4 + 0) * LDS_] = brg[j].x;
            d[(n4 + 1) * LDS_] = brg[j].y;
            d[(n4 + 2) * LDS_] = brg[j].z;
            d[(n4 + 3) * LDS_] = brg[j].w;
        }
    };

    auto compute = [&](int buf) {
        const float* a_ = sA + buf * TILE_F;
        const float* b_ = sB + buf * TILE_F;
#pragma unroll
        for (int ks = 0; ks < 4; ks++) {
            uint32_t af[4][4];
#pragma unroll
            for (int i = 0; i < 4; i++) {
                const float* ap = a_ + (wm + i * 16 + g) * LDS_ + ks * 8 + qt;
                af[i][0] = f2tf32(ap[0]);
                af[i][1] = f2tf32(ap[8 * LDS_]);
                af[i][2] = f2tf32(ap[4]);
                af[i][3] = f2tf32(ap[8 * LDS_ + 4]);
            }
            uint32_t bf[4][2];
#pragma unroll
            for (int jn = 0; jn < 4; jn++) {
                const float* bp = b_ + (wn + jn * 8 + g) * LDS_ + ks * 8 + qt;
                bf[jn][0] = f2tf32(bp[0]);
                bf[jn][1] = f2tf32(bp[4]);
            }
#pragma unroll
            for (int i = 0; i < 4; i++)
#pragma unroll
                for (int jn = 0; jn < 4; jn++)
                    asm volatile(
                        "mma.sync.aligned.m16n8k8.row.col.f32.tf32.tf32.f32 "
                        "{%0,%1,%2,%3}, {%4,%5,%6,%7}, {%8,%9}, {%0,%1,%2,%3};"
                        : "+f"(acc[i][jn][0]), "+f"(acc[i][jn][1]),
                          "+f"(acc[i][jn][2]), "+f"(acc[i][jn][3])
                        : "r"(af[i][0]), "r"(af[i][1]), "r"(af[i][2]), "r"(af[i][3]),
                          "r"(bf[jn][0]), "r"(bf[jn][1]));
        }
    };

    // prologue: tile 0 -> buffer 0
    cpA(0, 0);
    if (!TRB) cpB(0, 0); else { ldBreg(0); stBreg(0); }
    asm volatile("cp.async.commit_group;");
    asm volatile("cp.async.wait_group 0;" ::: "memory");
    __syncthreads();

    const int NTL = K >> 5;
    for (int kt = 0; kt < NTL; kt++) {
        const int b = kt & 1;
        if (kt + 1 < NTL) {
            const int k0 = (kt + 1) << 5;
            cpA(k0, b ^ 1);
            if (!TRB) cpB(k0, b ^ 1);
            else      ldBreg(k0);
            asm volatile("cp.async.commit_group;");
        }
        compute(b);
        if (kt + 1 < NTL) {
            if (TRB) stBreg(b ^ 1);
            asm volatile("cp.async.wait_group 0;" ::: "memory");
            __syncthreads();
        }
    }

    // ---- epilogue ----
#pragma unroll
    for (int i = 0; i < 4; i++) {
        const int row0 = rowBase + wm + i * 16 + g;
#pragma unroll
        for (int jn = 0; jn < 4; jn++) {
            const int col = colBase + wn + jn * 8 + qt * 2;
#pragma unroll
            for (int h = 0; h < 2; h++) {
                const int r = row0 + h * 8;
                float v0 = acc[i][jn][h * 2], v1 = acc[i][jn][h * 2 + 1];
                if (EPI == EPI_BIAS) {
                    v0 += bias[col]; v1 += bias[col + 1];
                } else if (EPI == EPI_BIAS_RELU) {
                    v0 = fmaxf(v0 + bias[col], 0.f);
                    v1 = fmaxf(v1 + bias[col + 1], 0.f);
                } else if (EPI == EPI_SCORE) {
                    v0 *= scale; v1 *= scale;
                    if (mask[(long)r * S_ + col] == 0)     v0 = -1e9f;
                    if (mask[(long)r * S_ + col + 1] == 0) v1 = -1e9f;
                }
                float2 o; o.x = v0; o.y = v1;
                *(float2*)(C + (long)r * ldc + col) = o;
            }
        }
    }
}

// ---------------- softmax: one warp per 1024-wide row ----------------------
__global__ void __launch_bounds__(256) softmax_kernel(float* __restrict__ s)
{
    const int gw   = (blockIdx.x * blockDim.x + threadIdx.x) >> 5;
    const int lane = threadIdx.x & 31;
    float* row = s + (size_t)gw * S_;

    float4 v[8];
    float mx = -3.4e38f;
#pragma unroll
    for (int i = 0; i < 8; i++) {
        v[i] = *(const float4*)&row[lane * 4 + i * 128];
        mx = fmaxf(mx, fmaxf(fmaxf(v[i].x, v[i].y), fmaxf(v[i].z, v[i].w)));
    }
#pragma unroll
    for (int o = 16; o; o >>= 1) mx = fmaxf(mx, __shfl_xor_sync(0xffffffffu, mx, o));

    float sum = 0.f;
#pragma unroll
    for (int i = 0; i < 8; i++) {
        v[i].x = __expf(v[i].x - mx);
        v[i].y = __expf(v[i].y - mx);
        v[i].z = __expf(v[i].z - mx);
        v[i].w = __expf(v[i].w - mx);
        sum += v[i].x + v[i].y + v[i].z + v[i].w;
    }
#pragma unroll
    for (int o = 16; o; o >>= 1) sum += __shfl_xor_sync(0xffffffffu, sum, o);

    const float inv = 1.f / sum;
#pragma unroll
    for (int i = 0; i < 8; i++) {
        v[i].x *= inv; v[i].y *= inv; v[i].z *= inv; v[i].w *= inv;
        *(float4*)&row[lane * 4 + i * 128] = v[i];
    }
}

// ---------------- fused residual + LayerNorm -------------------------------
__device__ __forceinline__ float blk_sum(float v, float* sh)
{
#pragma unroll
    for (int o = 16; o; o >>= 1) v += __shfl_xor_sync(0xffffffffu, v, o);
    const int lane = threadIdx.x & 31, w = threadIdx.x >> 5;
    if (lane == 0) sh[w] = v;
    __syncthreads();
    if (w == 0) {
        float t = (lane < 8) ? sh[lane] : 0.f;
#pragma unroll
        for (int o = 4; o; o >>= 1) t += __shfl_xor_sync(0xffu, t, o);
        if (lane == 0) sh[0] = t;
    }
    __syncthreads();
    const float r = sh[0];
    __syncthreads();
    return r;
}

__global__ void __launch_bounds__(256) ln_kernel(
    const float* __restrict__ a, const float* __restrict__ b,
    const float* __restrict__ g, const float* __restrict__ be,
    float* __restrict__ out)
{
    __shared__ float sh[8];
    const int row = blockIdx.x, tid = threadIdx.x;
    const float* pa = a + (size_t)row * D_;
    const float* pb = b + (size_t)row * D_;
    const int c0 = tid * 8;

    float x[8];
    {
        float4 a0 = *(const float4*)&pa[c0], a1 = *(const float4*)&pa[c0 + 4];
        float4 b0 = *(const float4*)&pb[c0], b1 = *(const float4*)&pb[c0 + 4];
        x[0] = a0.x + b0.x; x[1] = a0.y + b0.y; x[2] = a0.z + b0.z; x[3] = a0.w + b0.w;
        x[4] = a1.x + b1.x; x[5] = a1.y + b1.y; x[6] = a1.z + b1.z; x[7] = a1.w + b1.w;
    }
    float s = 0.f;
#pragma unroll
    for (int i = 0; i < 8; i++) s += x[i];
    const float mean = blk_sum(s, sh) * (1.f / D_);

    float vs = 0.f;
#pragma unroll
    for (int i = 0; i < 8; i++) { const float d = x[i] - mean; vs += d * d; }
    const float var = blk_sum(vs, sh) * (1.f / D_);
    const float inv = rsqrtf(var + 1e-5f);

    float4 g0 = *(const float4*)&g[c0],  g1v = *(const float4*)&g[c0 + 4];
    float4 e0 = *(const float4*)&be[c0], e1v = *(const float4*)&be[c0 + 4];
    float4 o0, o1;
    o0.x = (x[0] - mean) * inv * g0.x + e0.x;
    o0.y = (x[1] - mean) * inv * g0.y + e0.y;
    o0.z = (x[2] - mean) * inv * g0.z + e0.z;
    o0.w = (x[3] - mean) * inv * g0.w + e0.w;
    o1.x = (x[4] - mean) * inv * g1v.x + e1v.x;
    o1.y = (x[5] - mean) * inv * g1v.y + e1v.y;
    o1.z = (x[6] - mean) * inv * g1v.z + e1v.z;
    o1.w = (x[7] - mean) * inv * g1v.w + e1v.w;
    float* po = out + (size_t)row * D_;
    *(float4*)&po[c0] = o0;
    *(float4*)&po[c0 + 4] = o1;
}

// ---------------- launch ----------------------------------------------------
extern "C" void kernel_launch(void* const* d_in, const int* in_sizes, int n_in,
                              void* d_out, int out_size)
{
    const float* x    = (const float*)d_in[0];
    const int*   mask = (const int*)  d_in[1];
    const float* Wq = (const float*)d_in[2];  const float* bq = (const float*)d_in[3];
    const float* Wk = (const float*)d_in[4];  const float* bk = (const float*)d_in[5];
    const float* Wv = (const float*)d_in[6];  const float* bv = (const float*)d_in[7];
    const float* Wo = (const float*)d_in[8];  const float* bo = (const float*)d_in[9];
    const float* W1 = (const float*)d_in[10]; const float* b1 = (const float*)d_in[11];
    const float* W2 = (const float*)d_in[12]; const float* b2 = (const float*)d_in[13];
    const float* g1 = (const float*)d_in[14]; const float* be1 = (const float*)d_in[15];
    const float* g2 = (const float*)d_in[16]; const float* be2 = (const float*)d_in[17];
    float* out = (float*)d_out;

    float *q, *k, *v, *sc, *hb;
    cudaGetSymbolAddress((void**)&q,  g_q);
    cudaGetSymbolAddress((void**)&k,  g_k);
    cudaGetSymbolAddress((void**)&v,  g_v);
    cudaGetSymbolAddress((void**)&sc, g_s);
    cudaGetSymbolAddress((void**)&hb, g_h);

    const int SMEM = 4 * 128 * 36 * 4;   // 73728 bytes
    cudaFuncSetAttribute(mma_gemm<false, EPI_BIAS>,
                         cudaFuncAttributeMaxDynamicSharedMemorySize, SMEM);
    cudaFuncSetAttribute(mma_gemm<false, EPI_BIAS_RELU>,
                         cudaFuncAttributeMaxDynamicSharedMemorySize, SMEM);
    cudaFuncSetAttribute(mma_gemm<false, EPI_SCORE>,
                         cudaFuncAttributeMaxDynamicSharedMemorySize, SMEM);
    cudaFuncSetAttribute(mma_gemm<true, EPI_NONE>,
                         cudaFuncAttributeMaxDynamicSharedMemorySize, SMEM);

    const float scale = 0.08838834764831843f;  // 1/sqrt(128)
    const long SD = (long)S_ * D_;
    const long SS = (long)S_ * S_;

    // QKV projections: [8192,2048] = x @ W^T + b
    dim3 gproj(D_ / 128, NTOK / 128, 1);
    mma_gemm<false, EPI_BIAS><<<gproj, 256, SMEM>>>(
        x, D_, 0, 0, Wq, D_, 0, 0, q, D_, 0, 0, D_, 1, bq, nullptr, 0.f);
    mma_gemm<false, EPI_BIAS><<<gproj, 256, SMEM>>>(
        x, D_, 0, 0, Wk, D_, 0, 0, k, D_, 0, 0, D_, 1, bk, nullptr, 0.f);
    mma_gemm<false, EPI_BIAS><<<gproj, 256, SMEM>>>(
        x, D_, 0, 0, Wv, D_, 0, 0, v, D_, 0, 0, D_, 1, bv, nullptr, 0.f);

    // scores[b,h] = q_bh @ k_bh^T * scale, masked
    dim3 gsc(S_ / 128, S_ / 128, B_ * H_);
    mma_gemm<false, EPI_SCORE><<<gsc, 256, SMEM>>>(
        q, D_, SD, DH_, k, D_, SD, DH_,
        sc, S_, (long)H_ * SS, SS, DH_, H_, nullptr, mask, scale);

    // softmax
    softmax_kernel<<<(B_ * H_ * S_) / 8, 256>>>(sc);

    // attn @ V (B is [K,N] N-contig -> TRB) -> g_q
    dim3 gav(1, S_ / 128, B_ * H_);
    mma_gemm<true, EPI_NONE><<<gav, 256, SMEM>>>(
        sc, S_, (long)H_ * SS, SS, v, D_, SD, DH_,
        q, D_, SD, DH_, S_, H_, nullptr, nullptr, 0.f);

    // output projection -> g_k
    mma_gemm<false, EPI_BIAS><<<gproj, 256, SMEM>>>(
        q, D_, 0, 0, Wo, D_, 0, 0, k, D_, 0, 0, D_, 1, bo, nullptr, 0.f);

    // x1 = LN(attn_proj + x) -> g_v
    ln_kernel<<<NTOK, 256>>>(k, x, g1, be1, v);

    // h = relu(x1 @ W1^T + b1) -> g_h
    dim3 gff1(FF_ / 128, NTOK / 128, 1);
    mma_gemm<false, EPI_BIAS_RELU><<<gff1, 256, SMEM>>>(
        v, D_, 0, 0, W1, D_, 0, 0, hb, FF_, 0, 0, D_, 1, b1, nullptr, 0.f);

    // ffn = h @ W2^T + b2 -> g_k
    mma_gemm<false, EPI_BIAS><<<gproj, 256, SMEM>>>(
        hb, FF_, 0, 0, W2, FF_, 0, 0, k, D_, 0, 0, FF_, 1, b2, nullptr, 0.f);

    // out = LN(ffn + x1)
    ln_kernel<<<NTOK, 256>>>(k, v, g2, be2, out);
}

// round 5
// speedup vs baseline: 4.1013x; 1.2702x over previous
#include <cuda_runtime.h>
#include <cstdint>

#define B_   8
#define S_   1024
#define D_   2048
#define H_   16
#define DH_  128
#define FF_  8192
#define NTOK (B_*S_)   // 8192

// ---------------- scratch ----------------
__device__ float g_q[(size_t)NTOK * D_];            // q -> attn_out
__device__ float g_k[(size_t)NTOK * D_];            // k -> Wo out -> FFN2 out
__device__ float g_v[(size_t)NTOK * D_];            // v -> x1 exact
__device__ float g_s[(size_t)B_ * H_ * S_ * S_];    // scores / probs
__device__ float g_h[(size_t)NTOK * FF_];           // FFN hidden
__device__ float g_xr[(size_t)NTOK * D_];           // x rounded
__device__ float g_vt[(size_t)NTOK * D_];           // V transposed per head
__device__ float g_x1r[(size_t)NTOK * D_];          // x1 rounded
__device__ float g_wr[(size_t)(4 * D_ * D_ + 2 * FF_ * D_)]; // rounded weights

enum { EPI_NONE = 0, EPI_BIAS = 1, EPI_BIAS_RELU = 2, EPI_SCORE = 3 };

__device__ __forceinline__ uint32_t smem_u32(const void* p) {
    uint32_t a;
    asm("{ .reg .u64 t; cvta.to.shared.u64 t, %1; cvt.u32.u64 %0, t; }" : "=r"(a) : "l"(p));
    return a;
}
__device__ __forceinline__ float rnd_tf32(float f) {
    uint32_t r;
    asm("cvt.rna.tf32.f32 %0, %1;" : "=r"(r) : "f"(f));
    return __uint_as_float(r);
}

// ---------------- tf32 mma.sync GEMM (NT, operands pre-rounded) ------------
// C[128x128 tile] = A[M,K] @ B^T,  B is [N,K] row-major (K-contiguous).
template <int EPI, bool ROUND>
__global__ void __launch_bounds__(256, 2) mma_gemm(
    const float* __restrict__ A, int lda, long sAb, long sAh,
    const float* __restrict__ Bm, int ldb, long sBb, long sBh,
    float* __restrict__ C, int ldc, long sCb, long sCh,
    int K, int HH, const float* __restrict__ bias,
    const int* __restrict__ mask, float scale)
{
    extern __shared__ float sm[];
    const int tid = threadIdx.x, lane = tid & 31, wid = tid >> 5;

    const int z = blockIdx.z;
    A  += (long)(z / HH) * sAb + (long)(z % HH) * sAh;
    Bm += (long)(z / HH) * sBb + (long)(z % HH) * sBh;
    C  += (long)(z / HH) * sCb + (long)(z % HH) * sCh;

    const int rowBase = blockIdx.y * 128;
    const int colBase = blockIdx.x * 128;

    constexpr int LDSF   = 36;            // padded row stride (floats), 144B
    constexpr int TILE_F = 128 * LDSF;    // floats per buffer
    constexpr int STG    = 3;
    const uint32_t sA0 = smem_u32(sm);
    const uint32_t sB0 = sA0 + STG * TILE_F * 4;

    const int wm = (wid & 1) * 64;        // warp row offset
    const int wn = (wid >> 1) * 32;       // warp col offset
    const int g  = lane >> 2, qt = lane & 3;

    // ldmatrix source addresses (per-lane, byte units)
    const uint32_t aFrag = sA0 +
        (uint32_t)((wm + ((lane >> 3) & 1) * 8 + (lane & 7)) * 144) + (lane >> 4) * 16;
    const uint32_t bFrag = sB0 +
        (uint32_t)((wn + (lane & 7)) * 144) + ((lane >> 3) & 1) * 16;

    float acc[4][4][4];
#pragma unroll
    for (int i = 0; i < 4; i++)
#pragma unroll
        for (int j = 0; j < 4; j++)
#pragma unroll
            for (int u = 0; u < 4; u++) acc[i][j][u] = 0.f;

    auto issue = [&](int kt, int buf) {
        const int k0 = kt << 5;
#pragma unroll
        for (int j = 0; j < 4; j++) {
            int f = tid + 256 * j; int r = f >> 3, c4 = (f & 7) * 4;
            const float* sa = A + (long)(rowBase + r) * lda + k0 + c4;
            uint32_t da = sA0 + (uint32_t)(buf * TILE_F + r * LDSF + c4) * 4;
            asm volatile("cp.async.cg.shared.global [%0], [%1], 16;" :: "r"(da), "l"(sa));
            const float* sb = Bm + (long)(colBase + r) * ldb + k0 + c4;
            uint32_t db = sB0 + (uint32_t)(buf * TILE_F + r * LDSF + c4) * 4;
            asm volatile("cp.async.cg.shared.global [%0], [%1], 16;" :: "r"(db), "l"(sb));
        }
        asm volatile("cp.async.commit_group;");
    };

    auto compute = [&](int buf) {
        const uint32_t ab = aFrag + (uint32_t)(buf * TILE_F * 4);
        const uint32_t bb = bFrag + (uint32_t)(buf * TILE_F * 4);
#pragma unroll
        for (int ks = 0; ks < 4; ks++) {
            uint32_t af[4][4], bf[4][2];
#pragma unroll
            for (int i = 0; i < 4; i++)
                asm volatile("ldmatrix.sync.aligned.m8n8.x4.shared.b16 {%0,%1,%2,%3}, [%4];"
                    : "=r"(af[i][0]), "=r"(af[i][1]), "=r"(af[i][2]), "=r"(af[i][3])
                    : "r"(ab + ks * 32 + i * (16 * 144)));
#pragma unroll
            for (int jn = 0; jn < 4; jn++)
                asm volatile("ldmatrix.sync.aligned.m8n8.x2.shared.b16 {%0,%1}, [%2];"
                    : "=r"(bf[jn][0]), "=r"(bf[jn][1])
                    : "r"(bb + ks * 32 + jn * (8 * 144)));
#pragma unroll
            for (int i = 0; i < 4; i++)
#pragma unroll
                for (int jn = 0; jn < 4; jn++)
                    asm volatile(
                        "mma.sync.aligned.m16n8k8.row.col.f32.tf32.tf32.f32 "
                        "{%0,%1,%2,%3}, {%4,%5,%6,%7}, {%8,%9}, {%0,%1,%2,%3};"
                        : "+f"(acc[i][jn][0]), "+f"(acc[i][jn][1]),
                          "+f"(acc[i][jn][2]), "+f"(acc[i][jn][3])
                        : "r"(af[i][0]), "r"(af[i][1]), "r"(af[i][2]), "r"(af[i][3]),
                          "r"(bf[jn][0]), "r"(bf[jn][1]));
        }
    };

    const int NTL = K >> 5;
    issue(0, 0);
    issue(1, 1);
    for (int kt = 0; kt < NTL; kt++) {
        if (kt == NTL - 1) asm volatile("cp.async.wait_group 0;" ::: "memory");
        else               asm volatile("cp.async.wait_group 1;" ::: "memory");
        __syncthreads();
        if (kt + 2 < NTL) issue(kt + 2, (kt + 2) % STG);
        compute(kt % STG);
    }

    // ---- epilogue ----
#pragma unroll
    for (int i = 0; i < 4; i++) {
        const int row0 = rowBase + wm + i * 16 + g;
#pragma unroll
        for (int jn = 0; jn < 4; jn++) {
            const int col = colBase + wn + jn * 8 + qt * 2;
#pragma unroll
            for (int h = 0; h < 2; h++) {
                const int r = row0 + h * 8;
                float v0 = acc[i][jn][h * 2], v1 = acc[i][jn][h * 2 + 1];
                if (EPI == EPI_BIAS) {
                    v0 += bias[col]; v1 += bias[col + 1];
                } else if (EPI == EPI_BIAS_RELU) {
                    v0 = fmaxf(v0 + bias[col], 0.f);
                    v1 = fmaxf(v1 + bias[col + 1], 0.f);
                } else if (EPI == EPI_SCORE) {
                    v0 *= scale; v1 *= scale;
                    if (mask[(long)r * S_ + col] == 0)     v0 = -1e9f;
                    if (mask[(long)r * S_ + col + 1] == 0) v1 = -1e9f;
                }
                if (ROUND) { v0 = rnd_tf32(v0); v1 = rnd_tf32(v1); }
                float2 o; o.x = v0; o.y = v1;
                *(float2*)(C + (long)r * ldc + col) = o;
            }
        }
    }
}

// ---------------- round-copy (fp32 -> tf32-rounded fp32) -------------------
__global__ void __launch_bounds__(256) round_copy(
    const float4* __restrict__ in, float4* __restrict__ out, int n4)
{
    int i = blockIdx.x * blockDim.x + threadIdx.x;
    if (i < n4) {
        float4 v = in[i];
        v.x = rnd_tf32(v.x); v.y = rnd_tf32(v.y);
        v.z = rnd_tf32(v.z); v.w = rnd_tf32(v.w);
        out[i] = v;
    }
}

// ---------------- per-head V transpose: [S, Dh] -> [Dh, S] -----------------
__global__ void __launch_bounds__(256) transpose_v(
    const float* __restrict__ v, float* __restrict__ vt)
{
    __shared__ float t[32][33];
    const int bh = blockIdx.z, b = bh / H_, h = bh % H_;
    const int s0 = blockIdx.x * 32, d0 = blockIdx.y * 32;
    const int tx = threadIdx.x, ty = threadIdx.y;
#pragma unroll
    for (int rr = ty; rr < 32; rr += 8)
        t[rr][tx] = v[(size_t)(b * S_ + s0 + rr) * D_ + h * DH_ + d0 + tx];
    __syncthreads();
#pragma unroll
    for (int rr = ty; rr < 32; rr += 8)
        vt[(size_t)bh * DH_ * S_ + (size_t)(d0 + rr) * S_ + s0 + tx] = t[tx][rr];
}

// ---------------- softmax: one warp per 1024-wide row (rounds output) ------
__global__ void __launch_bounds__(256) softmax_kernel(float* __restrict__ s)
{
    const int gw   = (blockIdx.x * blockDim.x + threadIdx.x) >> 5;
    const int lane = threadIdx.x & 31;
    float* row = s + (size_t)gw * S_;

    float4 v[8];
    float mx = -3.4e38f;
#pragma unroll
    for (int i = 0; i < 8; i++) {
        v[i] = *(const float4*)&row[lane * 4 + i * 128];
        mx = fmaxf(mx, fmaxf(fmaxf(v[i].x, v[i].y), fmaxf(v[i].z, v[i].w)));
    }
#pragma unroll
    for (int o = 16; o; o >>= 1) mx = fmaxf(mx, __shfl_xor_sync(0xffffffffu, mx, o));

    float sum = 0.f;
#pragma unroll
    for (int i = 0; i < 8; i++) {
        v[i].x = __expf(v[i].x - mx);
        v[i].y = __expf(v[i].y - mx);
        v[i].z = __expf(v[i].z - mx);
        v[i].w = __expf(v[i].w - mx);
        sum += v[i].x + v[i].y + v[i].z + v[i].w;
    }
#pragma unroll
    for (int o = 16; o; o >>= 1) sum += __shfl_xor_sync(0xffffffffu, sum, o);

    const float inv = 1.f / sum;
#pragma unroll
    for (int i = 0; i < 8; i++) {
        v[i].x = rnd_tf32(v[i].x * inv);
        v[i].y = rnd_tf32(v[i].y * inv);
        v[i].z = rnd_tf32(v[i].z * inv);
        v[i].w = rnd_tf32(v[i].w * inv);
        *(float4*)&row[lane * 4 + i * 128] = v[i];
    }
}

// ---------------- fused residual + LayerNorm -------------------------------
__device__ __forceinline__ float blk_sum(float v, float* sh)
{
#pragma unroll
    for (int o = 16; o; o >>= 1) v += __shfl_xor_sync(0xffffffffu, v, o);
    const int lane = threadIdx.x & 31, w = threadIdx.x >> 5;
    if (lane == 0) sh[w] = v;
    __syncthreads();
    if (w == 0) {
        float t = (lane < 8) ? sh[lane] : 0.f;
#pragma unroll
        for (int o = 4; o; o >>= 1) t += __shfl_xor_sync(0xffu, t, o);
        if (lane == 0) sh[0] = t;
    }
    __syncthreads();
    const float r = sh[0];
    __syncthreads();
    return r;
}

template <bool DUAL>
__global__ void __launch_bounds__(256) ln_kernel(
    const float* __restrict__ a, const float* __restrict__ b,
    const float* __restrict__ g, const float* __restrict__ be,
    float* __restrict__ out, float* __restrict__ out_r)
{
    __shared__ float sh[8];
    const int row = blockIdx.x, tid = threadIdx.x;
    const float* pa = a + (size_t)row * D_;
    const float* pb = b + (size_t)row * D_;
    const int c0 = tid * 8;

    float x[8];
    {
        float4 a0 = *(const float4*)&pa[c0], a1 = *(const float4*)&pa[c0 + 4];
        float4 b0 = *(const float4*)&pb[c0], b1 = *(const float4*)&pb[c0 + 4];
        x[0] = a0.x + b0.x; x[1] = a0.y + b0.y; x[2] = a0.z + b0.z; x[3] = a0.w + b0.w;
        x[4] = a1.x + b1.x; x[5] = a1.y + b1.y; x[6] = a1.z + b1.z; x[7] = a1.w + b1.w;
    }
    float s = 0.f;
#pragma unroll
    for (int i = 0; i < 8; i++) s += x[i];
    const float mean = blk_sum(s, sh) * (1.f / D_);

    float vs = 0.f;
#pragma unroll
    for (int i = 0; i < 8; i++) { const float d = x[i] - mean; vs += d * d; }
    const float var = blk_sum(vs, sh) * (1.f / D_);
    const float inv = rsqrtf(var + 1e-5f);

    float o[8];
    float4 g0 = *(const float4*)&g[c0],  g1v = *(const float4*)&g[c0 + 4];
    float4 e0 = *(const float4*)&be[c0], e1v = *(const float4*)&be[c0 + 4];
    o[0] = (x[0] - mean) * inv * g0.x + e0.x;
    o[1] = (x[1] - mean) * inv * g0.y + e0.y;
    o[2] = (x[2] - mean) * inv * g0.z + e0.z;
    o[3] = (x[3] - mean) * inv * g0.w + e0.w;
    o[4] = (x[4] - mean) * inv * g1v.x + e1v.x;
    o[5] = (x[5] - mean) * inv * g1v.y + e1v.y;
    o[6] = (x[6] - mean) * inv * g1v.z + e1v.z;
    o[7] = (x[7] - mean) * inv * g1v.w + e1v.w;

    float* po = out + (size_t)row * D_;
    *(float4*)&po[c0]     = *(float4*)&o[0];
    *(float4*)&po[c0 + 4] = *(float4*)&o[4];
    if (DUAL) {
        float r[8];
#pragma unroll
        for (int i = 0; i < 8; i++) r[i] = rnd_tf32(o[i]);
        float* pr = out_r + (size_t)row * D_;
        *(float4*)&pr[c0]     = *(float4*)&r[0];
        *(float4*)&pr[c0 + 4] = *(float4*)&r[4];
    }
}

// ---------------- launch ----------------------------------------------------
extern "C" void kernel_launch(void* const* d_in, const int* in_sizes, int n_in,
                              void* d_out, int out_size)
{
    const float* x    = (const float*)d_in[0];
    const int*   mask = (const int*)  d_in[1];
    const float* Wq = (const float*)d_in[2];  const float* bq = (const float*)d_in[3];
    const float* Wk = (const float*)d_in[4];  const float* bk = (const float*)d_in[5];
    const float* Wv = (const float*)d_in[6];  const float* bv = (const float*)d_in[7];
    const float* Wo = (const float*)d_in[8];  const float* bo = (const float*)d_in[9];
    const float* W1 = (const float*)d_in[10]; const float* b1 = (const float*)d_in[11];
    const float* W2 = (const float*)d_in[12]; const float* b2 = (const float*)d_in[13];
    const float* g1 = (const float*)d_in[14]; const float* be1 = (const float*)d_in[15];
    const float* g2 = (const float*)d_in[16]; const float* be2 = (const float*)d_in[17];
    float* out = (float*)d_out;

    float *q, *k, *v, *sc, *hb, *xr, *vt, *x1r, *wr;
    cudaGetSymbolAddress((void**)&q,   g_q);
    cudaGetSymbolAddress((void**)&k,   g_k);
    cudaGetSymbolAddress((void**)&v,   g_v);
    cudaGetSymbolAddress((void**)&sc,  g_s);
    cudaGetSymbolAddress((void**)&hb,  g_h);
    cudaGetSymbolAddress((void**)&xr,  g_xr);
    cudaGetSymbolAddress((void**)&vt,  g_vt);
    cudaGetSymbolAddress((void**)&x1r, g_x1r);
    cudaGetSymbolAddress((void**)&wr,  g_wr);

    float* Wq_r = wr;
    float* Wk_r = wr + (size_t)D_ * D_;
    float* Wv_r = wr + (size_t)2 * D_ * D_;
    float* Wo_r = wr + (size_t)3 * D_ * D_;
    float* W1_r = wr + (size_t)4 * D_ * D_;
    float* W2_r = W1_r + (size_t)FF_ * D_;

    const int SMEM = 6 * 128 * 36 * 4;   // 110592 bytes (3 stages x A,B)
    cudaFuncSetAttribute(mma_gemm<EPI_BIAS, true>,
                         cudaFuncAttributeMaxDynamicSharedMemorySize, SMEM);
    cudaFuncSetAttribute(mma_gemm<EPI_BIAS, false>,
                         cudaFuncAttributeMaxDynamicSharedMemorySize, SMEM);
    cudaFuncSetAttribute(mma_gemm<EPI_BIAS_RELU, true>,
                         cudaFuncAttributeMaxDynamicSharedMemorySize, SMEM);
    cudaFuncSetAttribute(mma_gemm<EPI_SCORE, false>,
                         cudaFuncAttributeMaxDynamicSharedMemorySize, SMEM);
    cudaFuncSetAttribute(mma_gemm<EPI_NONE, true>,
                         cudaFuncAttributeMaxDynamicSharedMemorySize, SMEM);

    const float scale = 0.08838834764831843f;  // 1/sqrt(128)
    const long SD = (long)S_ * D_;
    const long SS = (long)S_ * S_;

    // ---- prep: round x + weights to tf32 ----
    auto rc = [&](const float* src, float* dst, size_t n) {
        int n4 = (int)(n / 4);
        round_copy<<<(n4 + 255) / 256, 256>>>((const float4*)src, (float4*)dst, n4);
    };
    rc(x,  xr,   (size_t)NTOK * D_);
    rc(Wq, Wq_r, (size_t)D_ * D_);
    rc(Wk, Wk_r, (size_t)D_ * D_);
    rc(Wv, Wv_r, (size_t)D_ * D_);
    rc(Wo, Wo_r, (size_t)D_ * D_);
    rc(W1, W1_r, (size_t)FF_ * D_);
    rc(W2, W2_r, (size_t)D_ * FF_);

    // ---- QKV projections ----
    dim3 gproj(D_ / 128, NTOK / 128, 1);
    mma_gemm<EPI_BIAS, true><<<gproj, 256, SMEM>>>(
        xr, D_, 0, 0, Wq_r, D_, 0, 0, q, D_, 0, 0, D_, 1, bq, nullptr, 0.f);
    mma_gemm<EPI_BIAS, true><<<gproj, 256, SMEM>>>(
        xr, D_, 0, 0, Wk_r, D_, 0, 0, k, D_, 0, 0, D_, 1, bk, nullptr, 0.f);
    mma_gemm<EPI_BIAS, true><<<gproj, 256, SMEM>>>(
        xr, D_, 0, 0, Wv_r, D_, 0, 0, v, D_, 0, 0, D_, 1, bv, nullptr, 0.f);

    // ---- scores + softmax ----
    dim3 gsc(S_ / 128, S_ / 128, B_ * H_);
    mma_gemm<EPI_SCORE, false><<<gsc, 256, SMEM>>>(
        q, D_, SD, DH_, k, D_, SD, DH_,
        sc, S_, (long)H_ * SS, SS, DH_, H_, nullptr, mask, scale);
    softmax_kernel<<<(B_ * H_ * S_) / 8, 256>>>(sc);

    // ---- V transpose, attn @ V ----
    dim3 gtr(S_ / 32, DH_ / 32, B_ * H_);
    transpose_v<<<gtr, dim3(32, 8, 1)>>>(v, vt);
    dim3 gav(DH_ / 128, S_ / 128, B_ * H_);
    mma_gemm<EPI_NONE, true><<<gav, 256, SMEM>>>(
        sc, S_, (long)H_ * SS, SS,
        vt, S_, (long)H_ * DH_ * S_, (long)DH_ * S_,
        q, D_, SD, DH_, S_, H_, nullptr, nullptr, 0.f);

    // ---- output projection, LN1 ----
    mma_gemm<EPI_BIAS, false><<<gproj, 256, SMEM>>>(
        q, D_, 0, 0, Wo_r, D_, 0, 0, k, D_, 0, 0, D_, 1, bo, nullptr, 0.f);
    ln_kernel<true><<<NTOK, 256>>>(k, x, g1, be1, v, x1r);   // v = x1 exact

    // ---- FFN ----
    dim3 gff1(FF_ / 128, NTOK / 128, 1);
    mma_gemm<EPI_BIAS_RELU, true><<<gff1, 256, SMEM>>>(
        x1r, D_, 0, 0, W1_r, D_, 0, 0, hb, FF_, 0, 0, D_, 1, b1, nullptr, 0.f);
    mma_gemm<EPI_BIAS, false><<<gproj, 256, SMEM>>>(
        hb, FF_, 0, 0, W2_r, FF_, 0, 0, k, D_, 0, 0, FF_, 1, b2, nullptr, 0.f);

    // ---- LN2 -> out ----
    ln_kernel<false><<<NTOK, 256>>>(k, v, g2, be2, out, nullptr);
}

// round 6
// speedup vs baseline: 6.8296x; 1.6652x over previous
#include <cuda_runtime.h>
#include <cuda_fp16.h>
#include <cstdint>

#define B_   8
#define S_   1024
#define D_   2048
#define H_   16
#define DH_  128
#define FF_  8192
#define NTOK (B_*S_)   // 8192

// ---------------- scratch ----------------
__device__ float  g_s[(size_t)B_ * H_ * S_ * S_];   // fp32 scores
__device__ float  g_k[(size_t)NTOK * D_];           // fp32: Wo out / FFN2 out
__device__ float  g_v[(size_t)NTOK * D_];           // fp32: x1 exact
__device__ __half h_x [(size_t)NTOK * D_];
__device__ __half h_q [(size_t)NTOK * D_];
__device__ __half h_k [(size_t)NTOK * D_];
__device__ __half h_v [(size_t)NTOK * D_];
__device__ __half h_vt[(size_t)NTOK * D_];
__device__ __half h_ao[(size_t)NTOK * D_];
__device__ __half h_x1[(size_t)NTOK * D_];
__device__ __half h_w [(size_t)(4 * D_ * D_ + 2 * FF_ * D_)];
__device__ __half h_p [(size_t)B_ * H_ * S_ * S_];  // fp16 probs
__device__ __half h_h [(size_t)NTOK * FF_];         // fp16 FFN hidden

enum { EPI_NONE = 0, EPI_BIAS = 1, EPI_BIAS_RELU = 2, EPI_SCORE = 3 };

__device__ __forceinline__ uint32_t smem_u32(const void* p) {
    uint32_t a;
    asm("{ .reg .u64 t; cvta.to.shared.u64 t, %1; cvt.u32.u64 %0, t; }" : "=r"(a) : "l"(p));
    return a;
}

// ---------------- fp16 mma.sync GEMM (NT; A,B fp16; fp32 accum) ------------
// C tile = 128(M) x BN(N);  A[M,K], B[N,K] row-major, K-contiguous halves.
template <int BN, int EPI, bool F16OUT>
__global__ void __launch_bounds__(256, (BN == 128 ? 2 : 1)) hgemm(
    const __half* __restrict__ A, int lda, long sAb, long sAh,
    const __half* __restrict__ Bm, int ldb, long sBb, long sBh,
    void* __restrict__ Cv, int ldc, long sCb, long sCh,
    int K, int HH, const float* __restrict__ bias,
    const int* __restrict__ mask, float scale)
{
    extern __shared__ __align__(16) char sm[];
    const int tid = threadIdx.x, lane = tid & 31, wid = tid >> 5;

    const int z = blockIdx.z;
    A  += (long)(z / HH) * sAb + (long)(z % HH) * sAh;
    Bm += (long)(z / HH) * sBb + (long)(z % HH) * sBh;
    const long coff = (long)(z / HH) * sCb + (long)(z % HH) * sCh;
    __half* Ch = (__half*)Cv + coff;
    float*  Cf = (float*)Cv + coff;

    const int rowBase = blockIdx.y * 128;
    const int colBase = blockIdx.x * BN;

    constexpr int WN  = BN / 4;     // warp N tile (64 or 32)
    constexpr int JN  = WN / 8;     // 8 or 4
    constexpr int JP  = JN / 2;     // ldmatrix.x4 pairs for B
    constexpr int ASTG = 128 * 64;  // bytes per A stage (64B rows)
    constexpr int BSTG = BN * 64;
    const uint32_t sA0 = smem_u32(sm);
    const uint32_t sB0 = sA0 + 3 * ASTG;

    const int wm = (wid & 1) * 64;
    const int wn = (wid >> 1) * WN;
    const int g  = lane >> 2, qt = lane & 3;

    // ldmatrix per-lane addresses (XOR-swizzled 64B rows)
    const int aR = wm + ((lane >> 3) & 1) * 8 + (lane & 7);
    const int aHi = lane >> 4, aSw = (aR >> 1) & 3;
    const uint32_t aRow = sA0 + (uint32_t)aR * 64;
    const uint32_t cA[2] = { (uint32_t)(((0 + aHi) ^ aSw) * 16),
                             (uint32_t)(((2 + aHi) ^ aSw) * 16) };
    const int bR = wn + ((lane >> 4) << 3) + (lane & 7);
    const int bHi = (lane >> 3) & 1, bSw = (bR >> 1) & 3;
    const uint32_t bRow = sB0 + (uint32_t)bR * 64;
    const uint32_t cB[2] = { (uint32_t)(((0 + bHi) ^ bSw) * 16),
                             (uint32_t)(((2 + bHi) ^ bSw) * 16) };

    float acc[4][JN][4];
#pragma unroll
    for (int i = 0; i < 4; i++)
#pragma unroll
        for (int j = 0; j < JN; j++)
#pragma unroll
            for (int u = 0; u < 4; u++) acc[i][j][u] = 0.f;

    auto issue = [&](int kt, int buf) {
        const int k0 = kt << 5;
#pragma unroll
        for (int j = 0; j < 2; j++) {
            int f = tid + 256 * j; int r = f >> 2, c = f & 3;
            const __half* src = A + (long)(rowBase + r) * lda + k0 + c * 8;
            uint32_t dst = sA0 + (uint32_t)(buf * ASTG + r * 64 + ((c ^ ((r >> 1) & 3)) * 16));
            asm volatile("cp.async.cg.shared.global [%0], [%1], 16;" :: "r"(dst), "l"(src));
        }
#pragma unroll
        for (int j = 0; j < BN / 64; j++) {
            int f = tid + 256 * j; int r = f >> 2, c = f & 3;
            const __half* src = Bm + (long)(colBase + r) * ldb + k0 + c * 8;
            uint32_t dst = sB0 + (uint32_t)(buf * BSTG + r * 64 + ((c ^ ((r >> 1) & 3)) * 16));
            asm volatile("cp.async.cg.shared.global [%0], [%1], 16;" :: "r"(dst), "l"(src));
        }
        asm volatile("cp.async.commit_group;");
    };

    auto compute = [&](int buf) {
        const uint32_t ab = aRow + (uint32_t)(buf * ASTG);
        const uint32_t bb = bRow + (uint32_t)(buf * BSTG);
#pragma unroll
        for (int ks = 0; ks < 2; ks++) {
            uint32_t af[4][4], bf[JN][2];
#pragma unroll
            for (int i = 0; i < 4; i++)
                asm volatile("ldmatrix.sync.aligned.m8n8.x4.shared.b16 {%0,%1,%2,%3}, [%4];"
                    : "=r"(af[i][0]), "=r"(af[i][1]), "=r"(af[i][2]), "=r"(af[i][3])
                    : "r"(ab + i * 1024 + cA[ks]));
#pragma unroll
            for (int p = 0; p < JP; p++)
                asm volatile("ldmatrix.sync.aligned.m8n8.x4.shared.b16 {%0,%1,%2,%3}, [%4];"
                    : "=r"(bf[2 * p][0]), "=r"(bf[2 * p][1]),
                      "=r"(bf[2 * p + 1][0]), "=r"(bf[2 * p + 1][1])
                    : "r"(bb + p * 1024 + cB[ks]));
#pragma unroll
            for (int i = 0; i < 4; i++)
#pragma unroll
                for (int jn = 0; jn < JN; jn++)
                    asm volatile(
                        "mma.sync.aligned.m16n8k16.row.col.f32.f16.f16.f32 "
                        "{%0,%1,%2,%3}, {%4,%5,%6,%7}, {%8,%9}, {%0,%1,%2,%3};"
                        : "+f"(acc[i][jn][0]), "+f"(acc[i][jn][1]),
                          "+f"(acc[i][jn][2]), "+f"(acc[i][jn][3])
                        : "r"(af[i][0]), "r"(af[i][1]), "r"(af[i][2]), "r"(af[i][3]),
                          "r"(bf[jn][0]), "r"(bf[jn][1]));
        }
    };

    const int NTL = K >> 5;
    issue(0, 0);
    issue(1, 1);
    for (int kt = 0; kt < NTL; kt++) {
        if (kt == NTL - 1) asm volatile("cp.async.wait_group 0;" ::: "memory");
        else               asm volatile("cp.async.wait_group 1;" ::: "memory");
        __syncthreads();
        if (kt + 2 < NTL) issue(kt + 2, (kt + 2) % 3);
        compute(kt % 3);
    }

    // ---- epilogue ----
#pragma unroll
    for (int i = 0; i < 4; i++) {
        const int row0 = rowBase + wm + i * 16 + g;
#pragma unroll
        for (int jn = 0; jn < JN; jn++) {
            const int col = colBase + wn + jn * 8 + qt * 2;
#pragma unroll
            for (int h = 0; h < 2; h++) {
                const int r = row0 + h * 8;
                float v0 = acc[i][jn][h * 2], v1 = acc[i][jn][h * 2 + 1];
                if (EPI == EPI_BIAS) {
                    v0 += bias[col]; v1 += bias[col + 1];
                } else if (EPI == EPI_BIAS_RELU) {
                    v0 = fmaxf(v0 + bias[col], 0.f);
                    v1 = fmaxf(v1 + bias[col + 1], 0.f);
                } else if (EPI == EPI_SCORE) {
                    v0 *= scale; v1 *= scale;
                    if (mask[(long)r * S_ + col] == 0)     v0 = -1e9f;
                    if (mask[(long)r * S_ + col + 1] == 0) v1 = -1e9f;
                }
                if (F16OUT) {
                    *(__half2*)(Ch + (long)r * ldc + col) = __floats2half2_rn(v0, v1);
                } else {
                    float2 o; o.x = v0; o.y = v1;
                    *(float2*)(Cf + (long)r * ldc + col) = o;
                }
            }
        }
    }
}

// ---------------- f32 -> f16 convert (8 elems/thread) ----------------------
__global__ void __launch_bounds__(256) f2h(
    const float4* __restrict__ in, uint4* __restrict__ out, int n8)
{
    int i = blockIdx.x * blockDim.x + threadIdx.x;
    if (i < n8) {
        float4 a = in[2 * i], b = in[2 * i + 1];
        __half2 q0 = __floats2half2_rn(a.x, a.y);
        __half2 q1 = __floats2half2_rn(a.z, a.w);
        __half2 q2 = __floats2half2_rn(b.x, b.y);
        __half2 q3 = __floats2half2_rn(b.z, b.w);
        uint4 u;
        u.x = *(uint32_t*)&q0; u.y = *(uint32_t*)&q1;
        u.z = *(uint32_t*)&q2; u.w = *(uint32_t*)&q3;
        out[i] = u;
    }
}

// ---------------- per-head V transpose (fp16): [S, Dh] -> [Dh, S] ----------
__global__ void __launch_bounds__(256) transpose_v(
    const __half* __restrict__ v, __half* __restrict__ vt)
{
    __shared__ __half t[32][34];
    const int bh = blockIdx.z, b = bh / H_, h = bh % H_;
    const int s0 = blockIdx.x * 32, d0 = blockIdx.y * 32;
    const int tx = threadIdx.x, ty = threadIdx.y;
#pragma unroll
    for (int rr = ty; rr < 32; rr += 8)
        t[rr][tx] = v[(size_t)(b * S_ + s0 + rr) * D_ + h * DH_ + d0 + tx];
    __syncthreads();
#pragma unroll
    for (int rr = ty; rr < 32; rr += 8)
        vt[(size_t)bh * DH_ * S_ + (size_t)(d0 + rr) * S_ + s0 + tx] = t[tx][rr];
}

// ---------------- softmax: fp32 scores -> fp16 probs -----------------------
__global__ void __launch_bounds__(256) softmax_kernel(
    const float* __restrict__ s, __half* __restrict__ p)
{
    const int gw   = (blockIdx.x * blockDim.x + threadIdx.x) >> 5;
    const int lane = threadIdx.x & 31;
    const float* row = s + (size_t)gw * S_;
    __half* prow = p + (size_t)gw * S_;

    float4 v[8];
    float mx = -3.4e38f;
#pragma unroll
    for (int i = 0; i < 8; i++) {
        v[i] = *(const float4*)&row[lane * 4 + i * 128];
        mx = fmaxf(mx, fmaxf(fmaxf(v[i].x, v[i].y), fmaxf(v[i].z, v[i].w)));
    }
#pragma unroll
    for (int o = 16; o; o >>= 1) mx = fmaxf(mx, __shfl_xor_sync(0xffffffffu, mx, o));

    float sum = 0.f;
#pragma unroll
    for (int i = 0; i < 8; i++) {
        v[i].x = __expf(v[i].x - mx);
        v[i].y = __expf(v[i].y - mx);
        v[i].z = __expf(v[i].z - mx);
        v[i].w = __expf(v[i].w - mx);
        sum += v[i].x + v[i].y + v[i].z + v[i].w;
    }
#pragma unroll
    for (int o = 16; o; o >>= 1) sum += __shfl_xor_sync(0xffffffffu, sum, o);

    const float inv = 1.f / sum;
#pragma unroll
    for (int i = 0; i < 8; i++) {
        const int c = lane * 4 + i * 128;
        *(__half2*)(prow + c)     = __floats2half2_rn(v[i].x * inv, v[i].y * inv);
        *(__half2*)(prow + c + 2) = __floats2half2_rn(v[i].z * inv, v[i].w * inv);
    }
}

// ---------------- fused residual + LayerNorm -------------------------------
__device__ __forceinline__ float blk_sum(float v, float* sh)
{
#pragma unroll
    for (int o = 16; o; o >>= 1) v += __shfl_xor_sync(0xffffffffu, v, o);
    const int lane = threadIdx.x & 31, w = threadIdx.x >> 5;
    if (lane == 0) sh[w] = v;
    __syncthreads();
    if (w == 0) {
        float t = (lane < 8) ? sh[lane] : 0.f;
#pragma unroll
        for (int o = 4; o; o >>= 1) t += __shfl_xor_sync(0xffu, t, o);
        if (lane == 0) sh[0] = t;
    }
    __syncthreads();
    const float r = sh[0];
    __syncthreads();
    return r;
}

template <bool DUAL>
__global__ void __launch_bounds__(256) ln_kernel(
    const float* __restrict__ a, const float* __restrict__ b,
    const float* __restrict__ g, const float* __restrict__ be,
    float* __restrict__ out, __half* __restrict__ out_h)
{
    __shared__ float sh[8];
    const int row = blockIdx.x, tid = threadIdx.x;
    const float* pa = a + (size_t)row * D_;
    const float* pb = b + (size_t)row * D_;
    const int c0 = tid * 8;

    float x[8];
    {
        float4 a0 = *(const float4*)&pa[c0], a1 = *(const float4*)&pa[c0 + 4];
        float4 b0 = *(const float4*)&pb[c0], b1 = *(const float4*)&pb[c0 + 4];
        x[0] = a0.x + b0.x; x[1] = a0.y + b0.y; x[2] = a0.z + b0.z; x[3] = a0.w + b0.w;
        x[4] = a1.x + b1.x; x[5] = a1.y + b1.y; x[6] = a1.z + b1.z; x[7] = a1.w + b1.w;
    }
    float s = 0.f;
#pragma unroll
    for (int i = 0; i < 8; i++) s += x[i];
    const float mean = blk_sum(s, sh) * (1.f / D_);

    float vs = 0.f;
#pragma unroll
    for (int i = 0; i < 8; i++) { const float d = x[i] - mean; vs += d * d; }
    const float var = blk_sum(vs, sh) * (1.f / D_);
    const float inv = rsqrtf(var + 1e-5f);

    float o[8];
    float4 g0 = *(const float4*)&g[c0],  g1v = *(const float4*)&g[c0 + 4];
    float4 e0 = *(const float4*)&be[c0], e1v = *(const float4*)&be[c0 + 4];
    o[0] = (x[0] - mean) * inv * g0.x + e0.x;
    o[1] = (x[1] - mean) * inv * g0.y + e0.y;
    o[2] = (x[2] - mean) * inv * g0.z + e0.z;
    o[3] = (x[3] - mean) * inv * g0.w + e0.w;
    o[4] = (x[4] - mean) * inv * g1v.x + e1v.x;
    o[5] = (x[5] - mean) * inv * g1v.y + e1v.y;
    o[6] = (x[6] - mean) * inv * g1v.z + e1v.z;
    o[7] = (x[7] - mean) * inv * g1v.w + e1v.w;

    float* po = out + (size_t)row * D_;
    *(float4*)&po[c0]     = *(float4*)&o[0];
    *(float4*)&po[c0 + 4] = *(float4*)&o[4];
    if (DUAL) {
        __half2* ph = (__half2*)(out_h + (size_t)row * D_ + c0);
        ph[0] = __floats2half2_rn(o[0], o[1]);
        ph[1] = __floats2half2_rn(o[2], o[3]);
        ph[2] = __floats2half2_rn(o[4], o[5]);
        ph[3] = __floats2half2_rn(o[6], o[7]);
    }
}

// ---------------- launch ----------------------------------------------------
extern "C" void kernel_launch(void* const* d_in, const int* in_sizes, int n_in,
                              void* d_out, int out_size)
{
    const float* x    = (const float*)d_in[0];
    const int*   mask = (const int*)  d_in[1];
    const float* Wq = (const float*)d_in[2];  const float* bq = (const float*)d_in[3];
    const float* Wk = (const float*)d_in[4];  const float* bk = (const float*)d_in[5];
    const float* Wv = (const float*)d_in[6];  const float* bv = (const float*)d_in[7];
    const float* Wo = (const float*)d_in[8];  const float* bo = (const float*)d_in[9];
    const float* W1 = (const float*)d_in[10]; const float* b1 = (const float*)d_in[11];
    const float* W2 = (const float*)d_in[12]; const float* b2 = (const float*)d_in[13];
    const float* g1 = (const float*)d_in[14]; const float* be1 = (const float*)d_in[15];
    const float* g2 = (const float*)d_in[16]; const float* be2 = (const float*)d_in[17];
    float* out = (float*)d_out;

    float *sc, *ko, *x1;
    __half *hx, *hq, *hk, *hv, *hvt, *hao, *hx1, *hw, *hp, *hh;
    cudaGetSymbolAddress((void**)&sc,  g_s);
    cudaGetSymbolAddress((void**)&ko,  g_k);
    cudaGetSymbolAddress((void**)&x1,  g_v);
    cudaGetSymbolAddress((void**)&hx,  h_x);
    cudaGetSymbolAddress((void**)&hq,  h_q);
    cudaGetSymbolAddress((void**)&hk,  h_k);
    cudaGetSymbolAddress((void**)&hv,  h_v);
    cudaGetSymbolAddress((void**)&hvt, h_vt);
    cudaGetSymbolAddress((void**)&hao, h_ao);
    cudaGetSymbolAddress((void**)&hx1, h_x1);
    cudaGetSymbolAddress((void**)&hw,  h_w);
    cudaGetSymbolAddress((void**)&hp,  h_p);
    cudaGetSymbolAddress((void**)&hh,  h_h);

    __half* hWq = hw;
    __half* hWk = hw + (size_t)D_ * D_;
    __half* hWv = hw + (size_t)2 * D_ * D_;
    __half* hWo = hw + (size_t)3 * D_ * D_;
    __half* hW1 = hw + (size_t)4 * D_ * D_;
    __half* hW2 = hW1 + (size_t)FF_ * D_;

    const int SMEM256 = 3 * (128 * 64 + 256 * 64);  // 73728
    const int SMEM128 = 3 * (128 * 64 + 128 * 64);  // 49152
    cudaFuncSetAttribute(hgemm<256, EPI_BIAS, true>,
                         cudaFuncAttributeMaxDynamicSharedMemorySize, SMEM256);
    cudaFuncSetAttribute(hgemm<256, EPI_BIAS, false>,
                         cudaFuncAttributeMaxDynamicSharedMemorySize, SMEM256);
    cudaFuncSetAttribute(hgemm<256, EPI_BIAS_RELU, true>,
                         cudaFuncAttributeMaxDynamicSharedMemorySize, SMEM256);
    cudaFuncSetAttribute(hgemm<256, EPI_SCORE, false>,
                         cudaFuncAttributeMaxDynamicSharedMemorySize, SMEM256);
    cudaFuncSetAttribute(hgemm<128, EPI_NONE, true>,
                         cudaFuncAttributeMaxDynamicSharedMemorySize, SMEM128);

    const float scale = 0.08838834764831843f;  // 1/sqrt(128)
    const long SD = (long)S_ * D_;
    const long SS = (long)S_ * S_;

    // ---- prep: convert x + weights to fp16 ----
    auto cv = [&](const float* src, __half* dst, size_t n) {
        int n8 = (int)(n / 8);
        f2h<<<(n8 + 255) / 256, 256>>>((const float4*)src, (uint4*)dst, n8);
    };
    cv(x,  hx,  (size_t)NTOK * D_);
    cv(Wq, hWq, (size_t)D_ * D_);
    cv(Wk, hWk, (size_t)D_ * D_);
    cv(Wv, hWv, (size_t)D_ * D_);
    cv(Wo, hWo, (size_t)D_ * D_);
    cv(W1, hW1, (size_t)FF_ * D_);
    cv(W2, hW2, (size_t)D_ * FF_);

    // ---- QKV projections (fp16 out) ----
    dim3 gproj(D_ / 256, NTOK / 128, 1);
    hgemm<256, EPI_BIAS, true><<<gproj, 256, SMEM256>>>(
        hx, D_, 0, 0, hWq, D_, 0, 0, hq, D_, 0, 0, D_, 1, bq, nullptr, 0.f);
    hgemm<256, EPI_BIAS, true><<<gproj, 256, SMEM256>>>(
        hx, D_, 0, 0, hWk, D_, 0, 0, hk, D_, 0, 0, D_, 1, bk, nullptr, 0.f);
    hgemm<256, EPI_BIAS, true><<<gproj, 256, SMEM256>>>(
        hx, D_, 0, 0, hWv, D_, 0, 0, hv, D_, 0, 0, D_, 1, bv, nullptr, 0.f);

    // ---- scores (fp32) + softmax (-> fp16 probs) ----
    dim3 gsc(S_ / 256, S_ / 128, B_ * H_);
    hgemm<256, EPI_SCORE, false><<<gsc, 256, SMEM256>>>(
        hq, D_, SD, DH_, hk, D_, SD, DH_,
        sc, S_, (long)H_ * SS, SS, DH_, H_, nullptr, mask, scale);
    softmax_kernel<<<(B_ * H_ * S_) / 8, 256>>>(sc, hp);

    // ---- V transpose, attn @ V (fp16 out) ----
    dim3 gtr(S_ / 32, DH_ / 32, B_ * H_);
    transpose_v<<<gtr, dim3(32, 8, 1)>>>(hv, hvt);
    dim3 gav(1, S_ / 128, B_ * H_);
    hgemm<128, EPI_NONE, true><<<gav, 256, SMEM128>>>(
        hp, S_, (long)H_ * SS, SS,
        hvt, S_, (long)H_ * DH_ * S_, (long)DH_ * S_,
        hao, D_, SD, DH_, S_, H_, nullptr, nullptr, 0.f);

    // ---- output projection (fp32 out), LN1 (dual out) ----
    hgemm<256, EPI_BIAS, false><<<gproj, 256, SMEM256>>>(
        hao, D_, 0, 0, hWo, D_, 0, 0, ko, D_, 0, 0, D_, 1, bo, nullptr, 0.f);
    ln_kernel<true><<<NTOK, 256>>>(ko, x, g1, be1, x1, hx1);

    // ---- FFN ----
    dim3 gff1(FF_ / 256, NTOK / 128, 1);
    hgemm<256, EPI_BIAS_RELU, true><<<gff1, 256, SMEM256>>>(
        hx1, D_, 0, 0, hW1, D_, 0, 0, hh, FF_, 0, 0, D_, 1, b1, nullptr, 0.f);
    hgemm<256, EPI_BIAS, false><<<gproj, 256, SMEM256>>>(
        hh, FF_, 0, 0, hW2, FF_, 0, 0, ko, D_, 0, 0, FF_, 1, b2, nullptr, 0.f);

    // ---- LN2 -> out ----
    ln_kernel<false><<<NTOK, 256>>>(ko, x1, g2, be2, out, nullptr);
}

// round 7
// speedup vs baseline: 7.5178x; 1.1008x over previous
#include <cuda_runtime.h>
#include <cuda_fp16.h>
#include <cstdint>

#define B_   8
#define S_   1024
#define D_   2048
#define H_   16
#define DH_  128
#define FF_  8192
#define NTOK (B_*S_)   // 8192

// ---------------- scratch ----------------
__device__ float  g_k[(size_t)NTOK * D_];           // fp32: Wo out / FFN2 out
__device__ float  g_v[(size_t)NTOK * D_];           // fp32: x1 exact
__device__ __half h_x [(size_t)NTOK * D_];
__device__ __half h_q [(size_t)NTOK * D_];
__device__ __half h_k [(size_t)NTOK * D_];
__device__ __half h_v [(size_t)NTOK * D_];
__device__ __half h_ao[(size_t)NTOK * D_];
__device__ __half h_x1[(size_t)NTOK * D_];
__device__ __half h_w [(size_t)(4 * D_ * D_ + 2 * FF_ * D_)];
__device__ __half h_h [(size_t)NTOK * FF_];         // fp16 FFN hidden

enum { EPI_NONE = 0, EPI_BIAS = 1, EPI_BIAS_RELU = 2, EPI_SCORE = 3 };

__device__ __forceinline__ uint32_t smem_u32(const void* p) {
    uint32_t a;
    asm("{ .reg .u64 t; cvta.to.shared.u64 t, %1; cvt.u32.u64 %0, t; }" : "=r"(a) : "l"(p));
    return a;
}

// ---------------- fp16 mma.sync GEMM (NT; A,B fp16; fp32 accum) ------------
template <int BN, int EPI, bool F16OUT>
__global__ void __launch_bounds__(256, (BN == 128 ? 2 : 1)) hgemm(
    const __half* __restrict__ A, int lda, long sAb, long sAh,
    const __half* __restrict__ Bm, int ldb, long sBb, long sBh,
    void* __restrict__ Cv, int ldc, long sCb, long sCh,
    int K, int HH, const float* __restrict__ bias,
    const int* __restrict__ mask, float scale)
{
    extern __shared__ __align__(16) char sm[];
    const int tid = threadIdx.x, lane = tid & 31, wid = tid >> 5;

    const int z = blockIdx.z;
    A  += (long)(z / HH) * sAb + (long)(z % HH) * sAh;
    Bm += (long)(z / HH) * sBb + (long)(z % HH) * sBh;
    const long coff = (long)(z / HH) * sCb + (long)(z % HH) * sCh;
    __half* Ch = (__half*)Cv + coff;
    float*  Cf = (float*)Cv + coff;

    const int rowBase = blockIdx.y * 128;
    const int colBase = blockIdx.x * BN;

    constexpr int WN  = BN / 4;
    constexpr int JN  = WN / 8;
    constexpr int JP  = JN / 2;
    constexpr int ASTG = 128 * 64;
    constexpr int BSTG = BN * 64;
    const uint32_t sA0 = smem_u32(sm);
    const uint32_t sB0 = sA0 + 3 * ASTG;

    const int wm = (wid & 1) * 64;
    const int wn = (wid >> 1) * WN;
    const int g  = lane >> 2, qt = lane & 3;

    const int aR = wm + ((lane >> 3) & 1) * 8 + (lane & 7);
    const int aHi = lane >> 4, aSw = (aR >> 1) & 3;
    const uint32_t aRow = sA0 + (uint32_t)aR * 64;
    const uint32_t cA[2] = { (uint32_t)(((0 + aHi) ^ aSw) * 16),
                             (uint32_t)(((2 + aHi) ^ aSw) * 16) };
    const int bR = wn + ((lane >> 4) << 3) + (lane & 7);
    const int bHi = (lane >> 3) & 1, bSw = (bR >> 1) & 3;
    const uint32_t bRow = sB0 + (uint32_t)bR * 64;
    const uint32_t cB[2] = { (uint32_t)(((0 + bHi) ^ bSw) * 16),
                             (uint32_t)(((2 + bHi) ^ bSw) * 16) };

    float acc[4][JN][4];
#pragma unroll
    for (int i = 0; i < 4; i++)
#pragma unroll
        for (int j = 0; j < JN; j++)
#pragma unroll
            for (int u = 0; u < 4; u++) acc[i][j][u] = 0.f;

    auto issue = [&](int kt, int buf) {
        const int k0 = kt << 5;
#pragma unroll
        for (int j = 0; j < 2; j++) {
            int f = tid + 256 * j; int r = f >> 2, c = f & 3;
            const __half* src = A + (long)(rowBase + r) * lda + k0 + c * 8;
            uint32_t dst = sA0 + (uint32_t)(buf * ASTG + r * 64 + ((c ^ ((r >> 1) & 3)) * 16));
            asm volatile("cp.async.cg.shared.global [%0], [%1], 16;" :: "r"(dst), "l"(src));
        }
#pragma unroll
        for (int j = 0; j < BN / 64; j++) {
            int f = tid + 256 * j; int r = f >> 2, c = f & 3;
            const __half* src = Bm + (long)(colBase + r) * ldb + k0 + c * 8;
            uint32_t dst = sB0 + (uint32_t)(buf * BSTG + r * 64 + ((c ^ ((r >> 1) & 3)) * 16));
            asm volatile("cp.async.cg.shared.global [%0], [%1], 16;" :: "r"(dst), "l"(src));
        }
        asm volatile("cp.async.commit_group;");
    };

    auto compute = [&](int buf) {
        const uint32_t ab = aRow + (uint32_t)(buf * ASTG);
        const uint32_t bb = bRow + (uint32_t)(buf * BSTG);
#pragma unroll
        for (int ks = 0; ks < 2; ks++) {
            uint32_t af[4][4], bf[JN][2];
#pragma unroll
            for (int i = 0; i < 4; i++)
                asm volatile("ldmatrix.sync.aligned.m8n8.x4.shared.b16 {%0,%1,%2,%3}, [%4];"
                    : "=r"(af[i][0]), "=r"(af[i][1]), "=r"(af[i][2]), "=r"(af[i][3])
                    : "r"(ab + i * 1024 + cA[ks]));
#pragma unroll
            for (int p = 0; p < JP; p++)
                asm volatile("ldmatrix.sync.aligned.m8n8.x4.shared.b16 {%0,%1,%2,%3}, [%4];"
                    : "=r"(bf[2 * p][0]), "=r"(bf[2 * p][1]),
                      "=r"(bf[2 * p + 1][0]), "=r"(bf[2 * p + 1][1])
                    : "r"(bb + p * 1024 + cB[ks]));
#pragma unroll
            for (int i = 0; i < 4; i++)
#pragma unroll
                for (int jn = 0; jn < JN; jn++)
                    asm volatile(
                        "mma.sync.aligned.m16n8k16.row.col.f32.f16.f16.f32 "
                        "{%0,%1,%2,%3}, {%4,%5,%6,%7}, {%8,%9}, {%0,%1,%2,%3};"
                        : "+f"(acc[i][jn][0]), "+f"(acc[i][jn][1]),
                          "+f"(acc[i][jn][2]), "+f"(acc[i][jn][3])
                        : "r"(af[i][0]), "r"(af[i][1]), "r"(af[i][2]), "r"(af[i][3]),
                          "r"(bf[jn][0]), "r"(bf[jn][1]));
        }
    };

    const int NTL = K >> 5;
    issue(0, 0);
    issue(1, 1);
    for (int kt = 0; kt < NTL; kt++) {
        if (kt == NTL - 1) asm volatile("cp.async.wait_group 0;" ::: "memory");
        else               asm volatile("cp.async.wait_group 1;" ::: "memory");
        __syncthreads();
        if (kt + 2 < NTL) issue(kt + 2, (kt + 2) % 3);
        compute(kt % 3);
    }

#pragma unroll
    for (int i = 0; i < 4; i++) {
        const int row0 = rowBase + wm + i * 16 + g;
#pragma unroll
        for (int jn = 0; jn < JN; jn++) {
            const int col = colBase + wn + jn * 8 + qt * 2;
#pragma unroll
            for (int h = 0; h < 2; h++) {
                const int r = row0 + h * 8;
                float v0 = acc[i][jn][h * 2], v1 = acc[i][jn][h * 2 + 1];
                if (EPI == EPI_BIAS) {
                    v0 += bias[col]; v1 += bias[col + 1];
                } else if (EPI == EPI_BIAS_RELU) {
                    v0 = fmaxf(v0 + bias[col], 0.f);
                    v1 = fmaxf(v1 + bias[col + 1], 0.f);
                } else if (EPI == EPI_SCORE) {
                    v0 *= scale; v1 *= scale;
                    if (mask[(long)r * S_ + col] == 0)     v0 = -1e9f;
                    if (mask[(long)r * S_ + col + 1] == 0) v1 = -1e9f;
                }
                if (F16OUT) {
                    *(__half2*)(Ch + (long)r * ldc + col) = __floats2half2_rn(v0, v1);
                } else {
                    float2 o; o.x = v0; o.y = v1;
                    *(float2*)(Cf + (long)r * ldc + col) = o;
                }
            }
        }
    }
}

// ---------------- flash attention: fused QK^T -> mask/softmax -> PV --------
// Grid: (S/128, B*H). 256 threads. Each warp owns 16 q rows.
// SMEM: Q[128x128h] + K[2][128x128h] + V[2][128x128h] = 160KB, rows 256B,
// chunk swizzle: cs = (c&8) | ((c&7) ^ (r&7))  (c = 16B chunk 0..15)
__global__ void __launch_bounds__(256, 1) flash_attn(
    const __half* __restrict__ Qg, const __half* __restrict__ Kg,
    const __half* __restrict__ Vg, const int* __restrict__ mask,
    __half* __restrict__ Og, float scale)
{
    extern __shared__ __align__(16) char sm[];
    const int tid = threadIdx.x, lane = tid & 31, wid = tid >> 5;
    const int g = lane >> 2, qt = lane & 3;
    const int qb = blockIdx.x, bh = blockIdx.y;
    const int b = bh >> 4, h = bh & 15;
    const size_t base = ((size_t)b * S_) * D_ + (size_t)h * DH_;
    const int q0 = qb * 128;

    const uint32_t sQ = smem_u32(sm);
    const uint32_t sK = sQ + 32768;
    const uint32_t sV = sK + 2 * 32768;

    auto ldtile = [&](uint32_t dst, const __half* src) {
#pragma unroll
        for (int j = 0; j < 8; j++) {
            int f = tid + 256 * j, r = f >> 4, c = f & 15;
            int cs = (c & 8) | ((c & 7) ^ (r & 7));
            const __half* s = src + (size_t)r * D_ + c * 8;
            uint32_t d = dst + r * 256 + cs * 16;
            asm volatile("cp.async.cg.shared.global [%0], [%1], 16;" :: "r"(d), "l"(s));
        }
    };

    ldtile(sQ, Qg + base + (size_t)q0 * D_);
    ldtile(sK, Kg + base);
    ldtile(sV, Vg + base);
    asm volatile("cp.async.commit_group;");
    ldtile(sK + 32768, Kg + base + (size_t)128 * D_);
    ldtile(sV + 32768, Vg + base + (size_t)128 * D_);
    asm volatile("cp.async.commit_group;");

    // preload Q A-fragments (constant across kv tiles)
    uint32_t afq[8][4];
    {
        asm volatile("cp.async.wait_group 1;" ::: "memory");
        __syncthreads();
        const int ar = wid * 16 + ((lane >> 3) & 1) * 8 + (lane & 7);
#pragma unroll
        for (int ks = 0; ks < 8; ks++) {
            int c = ks * 2 + (lane >> 4);
            int cs = (c & 8) | ((c & 7) ^ (ar & 7));
            asm volatile("ldmatrix.sync.aligned.m8n8.x4.shared.b16 {%0,%1,%2,%3}, [%4];"
                : "=r"(afq[ks][0]), "=r"(afq[ks][1]), "=r"(afq[ks][2]), "=r"(afq[ks][3])
                : "r"(sQ + ar * 256 + cs * 16));
        }
    }

    float acc_o[16][4];
#pragma unroll
    for (int p = 0; p < 16; p++)
#pragma unroll
        for (int u = 0; u < 4; u++) acc_o[p][u] = 0.f;
    float m0 = -3.4e38f, m1 = -3.4e38f, l0 = 0.f, l1 = 0.f;

    const int r0g = q0 + wid * 16 + g;
    const int* mrow0 = mask + (size_t)r0g * S_;
    const int* mrow1 = mask + (size_t)(r0g + 8) * S_;

    for (int t = 0; t < 8; t++) {
        if (t == 7) asm volatile("cp.async.wait_group 0;" ::: "memory");
        else        asm volatile("cp.async.wait_group 1;" ::: "memory");
        __syncthreads();

        const uint32_t kbuf = sK + (t & 1) * 32768;
        const uint32_t vbuf = sV + (t & 1) * 32768;
        const int kv0 = t * 128;

        // ---- phase A: S = Q @ K^T ----
        float sa[16][4];
#pragma unroll
        for (int p = 0; p < 16; p++)
#pragma unroll
            for (int u = 0; u < 4; u++) sa[p][u] = 0.f;
#pragma unroll
        for (int ks = 0; ks < 8; ks++) {
#pragma unroll
            for (int p = 0; p < 8; p++) {
                int br = p * 16 + ((lane >> 4) << 3) + (lane & 7);
                int c = ks * 2 + ((lane >> 3) & 1);
                int cs = (c & 8) | ((c & 7) ^ (br & 7));
                uint32_t b0, b1, b2, b3;
                asm volatile("ldmatrix.sync.aligned.m8n8.x4.shared.b16 {%0,%1,%2,%3}, [%4];"
                    : "=r"(b0), "=r"(b1), "=r"(b2), "=r"(b3)
                    : "r"(kbuf + br * 256 + cs * 16));
                asm volatile(
                    "mma.sync.aligned.m16n8k16.row.col.f32.f16.f16.f32 "
                    "{%0,%1,%2,%3}, {%4,%5,%6,%7}, {%8,%9}, {%0,%1,%2,%3};"
                    : "+f"(sa[2*p][0]), "+f"(sa[2*p][1]), "+f"(sa[2*p][2]), "+f"(sa[2*p][3])
                    : "r"(afq[ks][0]), "r"(afq[ks][1]), "r"(afq[ks][2]), "r"(afq[ks][3]),
                      "r"(b0), "r"(b1));
                asm volatile(
                    "mma.sync.aligned.m16n8k16.row.col.f32.f16.f16.f32 "
                    "{%0,%1,%2,%3}, {%4,%5,%6,%7}, {%8,%9}, {%0,%1,%2,%3};"
                    : "+f"(sa[2*p+1][0]), "+f"(sa[2*p+1][1]), "+f"(sa[2*p+1][2]), "+f"(sa[2*p+1][3])
                    : "r"(afq[ks][0]), "r"(afq[ks][1]), "r"(afq[ks][2]), "r"(afq[ks][3]),
                      "r"(b2), "r"(b3));
            }
        }

        // ---- phase B: scale + mask + online softmax ----
        float tm0 = -3.4e38f, tm1 = -3.4e38f;
#pragma unroll
        for (int j = 0; j < 16; j++) {
            int2 mk0 = *(const int2*)(mrow0 + kv0 + j * 8 + qt * 2);
            int2 mk1 = *(const int2*)(mrow1 + kv0 + j * 8 + qt * 2);
            sa[j][0] = (mk0.x == 0) ? -1e9f : sa[j][0] * scale;
            sa[j][1] = (mk0.y == 0) ? -1e9f : sa[j][1] * scale;
            sa[j][2] = (mk1.x == 0) ? -1e9f : sa[j][2] * scale;
            sa[j][3] = (mk1.y == 0) ? -1e9f : sa[j][3] * scale;
            tm0 = fmaxf(tm0, fmaxf(sa[j][0], sa[j][1]));
            tm1 = fmaxf(tm1, fmaxf(sa[j][2], sa[j][3]));
        }
        tm0 = fmaxf(tm0, __shfl_xor_sync(0xffffffffu, tm0, 1));
        tm0 = fmaxf(tm0, __shfl_xor_sync(0xffffffffu, tm0, 2));
        tm1 = fmaxf(tm1, __shfl_xor_sync(0xffffffffu, tm1, 1));
        tm1 = fmaxf(tm1, __shfl_xor_sync(0xffffffffu, tm1, 2));
        const float mn0 = fmaxf(m0, tm0), mn1 = fmaxf(m1, tm1);
        const float al0 = __expf(m0 - mn0), al1 = __expf(m1 - mn1);
        m0 = mn0; m1 = mn1;

        float ts0 = 0.f, ts1 = 0.f;
        uint32_t pa[8][4];
#pragma unroll
        for (int j2 = 0; j2 < 8; j2++) {
            float p0 = __expf(sa[2*j2][0]   - mn0), p1 = __expf(sa[2*j2][1]   - mn0);
            float p2 = __expf(sa[2*j2][2]   - mn1), p3 = __expf(sa[2*j2][3]   - mn1);
            float p4 = __expf(sa[2*j2+1][0] - mn0), p5 = __expf(sa[2*j2+1][1] - mn0);
            float p6 = __expf(sa[2*j2+1][2] - mn1), p7 = __expf(sa[2*j2+1][3] - mn1);
            ts0 += p0 + p1 + p4 + p5;
            ts1 += p2 + p3 + p6 + p7;
            __half2 q0h = __floats2half2_rn(p0, p1), q1h = __floats2half2_rn(p2, p3);
            __half2 q2h = __floats2half2_rn(p4, p5), q3h = __floats2half2_rn(p6, p7);
            pa[j2][0] = *(uint32_t*)&q0h; pa[j2][1] = *(uint32_t*)&q1h;
            pa[j2][2] = *(uint32_t*)&q2h; pa[j2][3] = *(uint32_t*)&q3h;
        }
        ts0 += __shfl_xor_sync(0xffffffffu, ts0, 1);
        ts0 += __shfl_xor_sync(0xffffffffu, ts0, 2);
        ts1 += __shfl_xor_sync(0xffffffffu, ts1, 1);
        ts1 += __shfl_xor_sync(0xffffffffu, ts1, 2);
        l0 = l0 * al0 + ts0;
        l1 = l1 * al1 + ts1;
#pragma unroll
        for (int p = 0; p < 16; p++) {
            acc_o[p][0] *= al0; acc_o[p][1] *= al0;
            acc_o[p][2] *= al1; acc_o[p][3] *= al1;
        }

        // ---- phase D: O += P @ V (ldmatrix.trans feeds V^T) ----
#pragma unroll
        for (int ks = 0; ks < 8; ks++) {
#pragma unroll
            for (int p = 0; p < 8; p++) {
                int vr = ks * 16 + ((lane >> 3) & 1) * 8 + (lane & 7);
                int c = p * 2 + ((lane >> 4) & 1);
                int cs = (c & 8) | ((c & 7) ^ (vr & 7));
                uint32_t b0, b1, b2, b3;
                asm volatile("ldmatrix.sync.aligned.m8n8.x4.trans.shared.b16 {%0,%1,%2,%3}, [%4];"
                    : "=r"(b0), "=r"(b1), "=r"(b2), "=r"(b3)
                    : "r"(vbuf + vr * 256 + cs * 16));
                asm volatile(
                    "mma.sync.aligned.m16n8k16.row.col.f32.f16.f16.f32 "
                    "{%0,%1,%2,%3}, {%4,%5,%6,%7}, {%8,%9}, {%0,%1,%2,%3};"
                    : "+f"(acc_o[2*p][0]), "+f"(acc_o[2*p][1]), "+f"(acc_o[2*p][2]), "+f"(acc_o[2*p][3])
                    : "r"(pa[ks][0]), "r"(pa[ks][1]), "r"(pa[ks][2]), "r"(pa[ks][3]),
                      "r"(b0), "r"(b1));
                asm volatile(
                    "mma.sync.aligned.m16n8k16.row.col.f32.f16.f16.f32 "
                    "{%0,%1,%2,%3}, {%4,%5,%6,%7}, {%8,%9}, {%0,%1,%2,%3};"
                    : "+f"(acc_o[2*p+1][0]), "+f"(acc_o[2*p+1][1]), "+f"(acc_o[2*p+1][2]), "+f"(acc_o[2*p+1][3])
                    : "r"(pa[ks][0]), "r"(pa[ks][1]), "r"(pa[ks][2]), "r"(pa[ks][3]),
                      "r"(b2), "r"(b3));
            }
        }

        __syncthreads();
        if (t + 2 < 8) {
            ldtile(sK + (t & 1) * 32768, Kg + base + (size_t)(t + 2) * 128 * D_);
            ldtile(sV + (t & 1) * 32768, Vg + base + (size_t)(t + 2) * 128 * D_);
            asm volatile("cp.async.commit_group;");
        }
    }

    // ---- epilogue: normalize, write fp16 ----
    const float i0 = 1.f / l0, i1 = 1.f / l1;
    __half* orow0 = Og + base + (size_t)(q0 + wid * 16 + g) * D_;
    __half* orow1 = orow0 + (size_t)8 * D_;
#pragma unroll
    for (int p = 0; p < 16; p++) {
        const int col = p * 8 + qt * 2;
        *(__half2*)(orow0 + col) = __floats2half2_rn(acc_o[p][0] * i0, acc_o[p][1] * i0);
        *(__half2*)(orow1 + col) = __floats2half2_rn(acc_o[p][2] * i1, acc_o[p][3] * i1);
    }
}

// ---------------- f32 -> f16 convert (8 elems/thread) ----------------------
__global__ void __launch_bounds__(256) f2h(
    const float4* __restrict__ in, uint4* __restrict__ out, int n8)
{
    int i = blockIdx.x * blockDim.x + threadIdx.x;
    if (i < n8) {
        float4 a = in[2 * i], b = in[2 * i + 1];
        __half2 q0 = __floats2half2_rn(a.x, a.y);
        __half2 q1 = __floats2half2_rn(a.z, a.w);
        __half2 q2 = __floats2half2_rn(b.x, b.y);
        __half2 q3 = __floats2half2_rn(b.z, b.w);
        uint4 u;
        u.x = *(uint32_t*)&q0; u.y = *(uint32_t*)&q1;
        u.z = *(uint32_t*)&q2; u.w = *(uint32_t*)&q3;
        out[i] = u;
    }
}

// ---------------- fused residual + LayerNorm -------------------------------
__device__ __forceinline__ float blk_sum(float v, float* sh)
{
#pragma unroll
    for (int o = 16; o; o >>= 1) v += __shfl_xor_sync(0xffffffffu, v, o);
    const int lane = threadIdx.x & 31, w = threadIdx.x >> 5;
    if (lane == 0) sh[w] = v;
    __syncthreads();
    if (w == 0) {
        float t = (lane < 8) ? sh[lane] : 0.f;
#pragma unroll
        for (int o = 4; o; o >>= 1) t += __shfl_xor_sync(0xffu, t, o);
        if (lane == 0) sh[0] = t;
    }
    __syncthreads();
    const float r = sh[0];
    __syncthreads();
    return r;
}

template <bool DUAL>
__global__ void __launch_bounds__(256) ln_kernel(
    const float* __restrict__ a, const float* __restrict__ b,
    const float* __restrict__ g, const float* __restrict__ be,
    float* __restrict__ out, __half* __restrict__ out_h)
{
    __shared__ float sh[8];
    const int row = blockIdx.x, tid = threadIdx.x;
    const float* pa = a + (size_t)row * D_;
    const float* pb = b + (size_t)row * D_;
    const int c0 = tid * 8;

    float x[8];
    {
        float4 a0 = *(const float4*)&pa[c0], a1 = *(const float4*)&pa[c0 + 4];
        float4 b0 = *(const float4*)&pb[c0], b1 = *(const float4*)&pb[c0 + 4];
        x[0] = a0.x + b0.x; x[1] = a0.y + b0.y; x[2] = a0.z + b0.z; x[3] = a0.w + b0.w;
        x[4] = a1.x + b1.x; x[5] = a1.y + b1.y; x[6] = a1.z + b1.z; x[7] = a1.w + b1.w;
    }
    float s = 0.f;
#pragma unroll
    for (int i = 0; i < 8; i++) s += x[i];
    const float mean = blk_sum(s, sh) * (1.f / D_);

    float vs = 0.f;
#pragma unroll
    for (int i = 0; i < 8; i++) { const float d = x[i] - mean; vs += d * d; }
    const float var = blk_sum(vs, sh) * (1.f / D_);
    const float inv = rsqrtf(var + 1e-5f);

    float o[8];
    float4 g0 = *(const float4*)&g[c0],  g1v = *(const float4*)&g[c0 + 4];
    float4 e0 = *(const float4*)&be[c0], e1v = *(const float4*)&be[c0 + 4];
    o[0] = (x[0] - mean) * inv * g0.x + e0.x;
    o[1] = (x[1] - mean) * inv * g0.y + e0.y;
    o[2] = (x[2] - mean) * inv * g0.z + e0.z;
    o[3] = (x[3] - mean) * inv * g0.w + e0.w;
    o[4] = (x[4] - mean) * inv * g1v.x + e1v.x;
    o[5] = (x[5] - mean) * inv * g1v.y + e1v.y;
    o[6] = (x[6] - mean) * inv * g1v.z + e1v.z;
    o[7] = (x[7] - mean) * inv * g1v.w + e1v.w;

    float* po = out + (size_t)row * D_;
    *(float4*)&po[c0]     = *(float4*)&o[0];
    *(float4*)&po[c0 + 4] = *(float4*)&o[4];
    if (DUAL) {
        __half2* ph = (__half2*)(out_h + (size_t)row * D_ + c0);
        ph[0] = __floats2half2_rn(o[0], o[1]);
        ph[1] = __floats2half2_rn(o[2], o[3]);
        ph[2] = __floats2half2_rn(o[4], o[5]);
        ph[3] = __floats2half2_rn(o[6], o[7]);
    }
}

// ---------------- launch ----------------------------------------------------
extern "C" void kernel_launch(void* const* d_in, const int* in_sizes, int n_in,
                              void* d_out, int out_size)
{
    const float* x    = (const float*)d_in[0];
    const int*   mask = (const int*)  d_in[1];
    const float* Wq = (const float*)d_in[2];  const float* bq = (const float*)d_in[3];
    const float* Wk = (const float*)d_in[4];  const float* bk = (const float*)d_in[5];
    const float* Wv = (const float*)d_in[6];  const float* bv = (const float*)d_in[7];
    const float* Wo = (const float*)d_in[8];  const float* bo = (const float*)d_in[9];
    const float* W1 = (const float*)d_in[10]; const float* b1 = (const float*)d_in[11];
    const float* W2 = (const float*)d_in[12]; const float* b2 = (const float*)d_in[13];
    const float* g1 = (const float*)d_in[14]; const float* be1 = (const float*)d_in[15];
    const float* g2 = (const float*)d_in[16]; const float* be2 = (const float*)d_in[17];
    float* out = (float*)d_out;

    float *ko, *x1;
    __half *hx, *hq, *hk, *hv, *hao, *hx1, *hw, *hh;
    cudaGetSymbolAddress((void**)&ko,  g_k);
    cudaGetSymbolAddress((void**)&x1,  g_v);
    cudaGetSymbolAddress((void**)&hx,  h_x);
    cudaGetSymbolAddress((void**)&hq,  h_q);
    cudaGetSymbolAddress((void**)&hk,  h_k);
    cudaGetSymbolAddress((void**)&hv,  h_v);
    cudaGetSymbolAddress((void**)&hao, h_ao);
    cudaGetSymbolAddress((void**)&hx1, h_x1);
    cudaGetSymbolAddress((void**)&hw,  h_w);
    cudaGetSymbolAddress((void**)&hh,  h_h);

    __half* hWq = hw;
    __half* hWk = hw + (size_t)D_ * D_;
    __half* hWv = hw + (size_t)2 * D_ * D_;
    __half* hWo = hw + (size_t)3 * D_ * D_;
    __half* hW1 = hw + (size_t)4 * D_ * D_;
    __half* hW2 = hW1 + (size_t)FF_ * D_;

    const int SMEM256 = 3 * (128 * 64 + 256 * 64);  // 73728
    const int SMEM_FA = 5 * 32768;                   // 163840
    cudaFuncSetAttribute(hgemm<256, EPI_BIAS, true>,
                         cudaFuncAttributeMaxDynamicSharedMemorySize, SMEM256);
    cudaFuncSetAttribute(hgemm<256, EPI_BIAS, false>,
                         cudaFuncAttributeMaxDynamicSharedMemorySize, SMEM256);
    cudaFuncSetAttribute(hgemm<256, EPI_BIAS_RELU, true>,
                         cudaFuncAttributeMaxDynamicSharedMemorySize, SMEM256);
    cudaFuncSetAttribute(flash_attn,
                         cudaFuncAttributeMaxDynamicSharedMemorySize, SMEM_FA);

    const float scale = 0.08838834764831843f;  // 1/sqrt(128)

    // ---- prep: convert x + weights to fp16 ----
    auto cv = [&](const float* src, __half* dst, size_t n) {
        int n8 = (int)(n / 8);
        f2h<<<(n8 + 255) / 256, 256>>>((const float4*)src, (uint4*)dst, n8);
    };
    cv(x,  hx,  (size_t)NTOK * D_);
    cv(Wq, hWq, (size_t)D_ * D_);
    cv(Wk, hWk, (size_t)D_ * D_);
    cv(Wv, hWv, (size_t)D_ * D_);
    cv(Wo, hWo, (size_t)D_ * D_);
    cv(W1, hW1, (size_t)FF_ * D_);
    cv(W2, hW2, (size_t)D_ * FF_);

    // ---- QKV projections (fp16 out) ----
    dim3 gproj(D_ / 256, NTOK / 128, 1);
    hgemm<256, EPI_BIAS, true><<<gproj, 256, SMEM256>>>(
        hx, D_, 0, 0, hWq, D_, 0, 0, hq, D_, 0, 0, D_, 1, bq, nullptr, 0.f);
    hgemm<256, EPI_BIAS, true><<<gproj, 256, SMEM256>>>(
        hx, D_, 0, 0, hWk, D_, 0, 0, hk, D_, 0, 0, D_, 1, bk, nullptr, 0.f);
    hgemm<256, EPI_BIAS, true><<<gproj, 256, SMEM256>>>(
        hx, D_, 0, 0, hWv, D_, 0, 0, hv, D_, 0, 0, D_, 1, bv, nullptr, 0.f);

    // ---- fused attention ----
    flash_attn<<<dim3(S_ / 128, B_ * H_), 256, SMEM_FA>>>(
        hq, hk, hv, mask, hao, scale);

    // ---- output projection (fp32 out), LN1 (dual out) ----
    hgemm<256, EPI_BIAS, false><<<gproj, 256, SMEM256>>>(
        hao, D_, 0, 0, hWo, D_, 0, 0, ko, D_, 0, 0, D_, 1, bo, nullptr, 0.f);
    ln_kernel<true><<<NTOK, 256>>>(ko, x, g1, be1, x1, hx1);

    // ---- FFN ----
    dim3 gff1(FF_ / 256, NTOK / 128, 1);
    hgemm<256, EPI_BIAS_RELU, true><<<gff1, 256, SMEM256>>>(
        hx1, D_, 0, 0, hW1, D_, 0, 0, hh, FF_, 0, 0, D_, 1, b1, nullptr, 0.f);
    hgemm<256, EPI_BIAS, false><<<gproj, 256, SMEM256>>>(
        hh, FF_, 0, 0, hW2, FF_, 0, 0, ko, D_, 0, 0, FF_, 1, b2, nullptr, 0.f);

    // ---- LN2 -> out ----
    ln_kernel<false><<<NTOK, 256>>>(ko, x1, g2, be2, out, nullptr);
}